// round 2
// baseline (speedup 1.0000x reference)
#include <cuda_runtime.h>
#include <cuda_bf16.h>

#define BB 2
#define LL 2048
#define DM 1024
#define NH 16
#define DK 64
#define MM (BB*LL)          // 4096 token rows
#define QT 64               // query tile
#define KT 64               // key tile
#define SROW 68             // padded smem row stride (floats, mult of 4)

// ---------------- scratch (device globals; no allocation allowed) ----------
__device__ float g_Q[BB*NH*LL*DK];      // [b][h][l][d]
__device__ float g_K[BB*NH*LL*DK];
__device__ float g_V[BB*NH*LL*DK];
__device__ float g_O[MM*DM];            // [b][l][D]  (attn @ V, normalized)
__device__ float g_inv[BB*NH*LL];       // 1/rowsum per (b,h,q)

// ============================================================================
// QKV projection: Q/K/V = x @ W^T + b, stored permuted as [b][h][l][d]
// Classic 128x128 tile, BK=8, 8x8 per thread, 256 threads.
// ============================================================================
__global__ __launch_bounds__(256) void qkv_proj_kernel(
    const float* __restrict__ x,
    const float* __restrict__ Wq, const float* __restrict__ Wk, const float* __restrict__ Wv,
    const float* __restrict__ bq, const float* __restrict__ bk, const float* __restrict__ bv)
{
    __shared__ float As[8][128];
    __shared__ float Bs[8][128];

    const int z = blockIdx.z;
    const float* W  = (z == 0) ? Wq : (z == 1 ? Wk : Wv);
    const float* bi = (z == 0) ? bq : (z == 1 ? bk : bv);
    float* dst      = (z == 0) ? g_Q : (z == 1 ? g_K : g_V);

    const int bm = blockIdx.y * 128;
    const int bn = blockIdx.x * 128;
    const int tid = threadIdx.x;
    const int tr = (tid >> 4) << 3;     // 0..120
    const int tc = (tid & 15) << 3;     // 0..120
    const int lr = tid >> 1;            // 0..127
    const int lk = (tid & 1) << 2;      // 0 or 4

    float acc[8][8];
    #pragma unroll
    for (int i = 0; i < 8; i++)
        #pragma unroll
        for (int j = 0; j < 8; j++) acc[i][j] = 0.f;

    for (int k0 = 0; k0 < DM; k0 += 8) {
        float4 av  = *(const float4*)(x + (size_t)(bm + lr) * DM + k0 + lk);
        float4 bv4 = *(const float4*)(W + (size_t)(bn + lr) * DM + k0 + lk);
        As[lk + 0][lr] = av.x;  As[lk + 1][lr] = av.y;
        As[lk + 2][lr] = av.z;  As[lk + 3][lr] = av.w;
        Bs[lk + 0][lr] = bv4.x; Bs[lk + 1][lr] = bv4.y;
        Bs[lk + 2][lr] = bv4.z; Bs[lk + 3][lr] = bv4.w;
        __syncthreads();
        #pragma unroll
        for (int k = 0; k < 8; k++) {
            float4 a0 = *(const float4*)(&As[k][tr]);
            float4 a1 = *(const float4*)(&As[k][tr + 4]);
            float4 b0 = *(const float4*)(&Bs[k][tc]);
            float4 b1 = *(const float4*)(&Bs[k][tc + 4]);
            float a[8] = {a0.x, a0.y, a0.z, a0.w, a1.x, a1.y, a1.z, a1.w};
            float b[8] = {b0.x, b0.y, b0.z, b0.w, b1.x, b1.y, b1.z, b1.w};
            #pragma unroll
            for (int i = 0; i < 8; i++)
                #pragma unroll
                for (int j = 0; j < 8; j++) acc[i][j] += a[i] * b[j];
        }
        __syncthreads();
    }

    #pragma unroll
    for (int i = 0; i < 8; i++) {
        int m = bm + tr + i;
        int bidx = m / LL;
        int l = m % LL;
        #pragma unroll
        for (int j = 0; j < 8; j++) {
            int o = bn + tc + j;
            int h = o >> 6;
            int d = o & 63;
            dst[(((size_t)bidx * NH + h) * LL + l) * DK + d] = acc[i][j] + bi[o];
        }
    }
}

// ============================================================================
// Fused attention block: per (b,h,qtile of 64): S = Q K^T / 8, e = exp(S)
// (masked -> 0), write unnormalized e to attn, accumulate rowsum and e@V,
// scale O by 1/rowsum, store O in [b][l][D] layout.
// 256 threads; 16x16 thread grid, 4x4 per thread over a 64x64 tile.
// ============================================================================
__global__ __launch_bounds__(256) void attn_kernel(
    const int* __restrict__ mask, float* __restrict__ attn_out)
{
    extern __shared__ char smem_raw[];
    float* Qs = (float*)smem_raw;                 // [d][q]  transposed, stride SROW
    float* Ks = Qs + 64 * SROW;                   // [d][k]  transposed
    float* Ps = Ks + 64 * SROW;                   // [q][k]  natural
    float* Vs = Ps + 64 * SROW;                   // [k][d]  natural
    int*   Ms = (int*)(Vs + 64 * SROW);           // [64]

    const int bh = blockIdx.y;                    // 0..31
    const int b  = bh >> 4;
    const int h  = bh & 15;
    const int q0 = blockIdx.x * QT;

    const float* Qb = g_Q + ((size_t)bh * LL + q0) * DK;
    const float* Kb = g_K + (size_t)bh * LL * DK;
    const float* Vb = g_V + (size_t)bh * LL * DK;

    const int tid = threadIdx.x;
    const int tq  = tid >> 4;     // 0..15
    const int tk  = tid & 15;     // 0..15

    // load Q tile transposed
    #pragma unroll
    for (int i = 0; i < 4; i++) {
        int idx = tid + i * 256;
        int q   = idx >> 4;
        int dg  = (idx & 15) << 2;
        float4 v = *(const float4*)(Qb + q * DK + dg);
        Qs[(dg + 0) * SROW + q] = v.x;
        Qs[(dg + 1) * SROW + q] = v.y;
        Qs[(dg + 2) * SROW + q] = v.z;
        Qs[(dg + 3) * SROW + q] = v.w;
    }

    float o[4][4];
    #pragma unroll
    for (int i = 0; i < 4; i++)
        #pragma unroll
        for (int j = 0; j < 4; j++) o[i][j] = 0.f;
    float rs[4] = {0.f, 0.f, 0.f, 0.f};

    for (int kt = 0; kt < LL / KT; kt++) {
        const float* Kt = Kb + kt * KT * DK;
        const float* Vt = Vb + kt * KT * DK;
        #pragma unroll
        for (int i = 0; i < 4; i++) {
            int idx = tid + i * 256;
            int r   = idx >> 4;
            int dg  = (idx & 15) << 2;
            float4 kv = *(const float4*)(Kt + r * DK + dg);
            Ks[(dg + 0) * SROW + r] = kv.x;
            Ks[(dg + 1) * SROW + r] = kv.y;
            Ks[(dg + 2) * SROW + r] = kv.z;
            Ks[(dg + 3) * SROW + r] = kv.w;
            *(float4*)(Vs + r * SROW + dg) = *(const float4*)(Vt + r * DK + dg);
        }
        if (tid < 64) Ms[tid] = mask[b * LL + kt * KT + tid];
        __syncthreads();

        // S = Q K^T
        float s[4][4];
        #pragma unroll
        for (int i = 0; i < 4; i++)
            #pragma unroll
            for (int j = 0; j < 4; j++) s[i][j] = 0.f;
        #pragma unroll
        for (int d = 0; d < 64; d++) {
            float4 a = *(const float4*)(Qs + d * SROW + (tq << 2));
            float4 k4 = *(const float4*)(Ks + d * SROW + (tk << 2));
            s[0][0] += a.x * k4.x; s[0][1] += a.x * k4.y; s[0][2] += a.x * k4.z; s[0][3] += a.x * k4.w;
            s[1][0] += a.y * k4.x; s[1][1] += a.y * k4.y; s[1][2] += a.y * k4.z; s[1][3] += a.y * k4.w;
            s[2][0] += a.z * k4.x; s[2][1] += a.z * k4.y; s[2][2] += a.z * k4.z; s[2][3] += a.z * k4.w;
            s[3][0] += a.w * k4.x; s[3][1] += a.w * k4.y; s[3][2] += a.w * k4.z; s[3][3] += a.w * k4.w;
        }

        // e = exp(s/8) with mask; rowsum; stash to Ps; emit unnormalized attn
        int mj[4];
        #pragma unroll
        for (int j = 0; j < 4; j++) mj[j] = Ms[(tk << 2) + j];
        #pragma unroll
        for (int i = 0; i < 4; i++) {
            #pragma unroll
            for (int j = 0; j < 4; j++) {
                float e = mj[j] ? __expf(s[i][j] * 0.125f) : 0.f;
                s[i][j] = e;
                rs[i] += e;
            }
            *(float4*)(Ps + ((tq << 2) + i) * SROW + (tk << 2)) =
                make_float4(s[i][0], s[i][1], s[i][2], s[i][3]);
            if (attn_out) {
                size_t row = (size_t)bh * LL + q0 + (tq << 2) + i;
                *(float4*)(attn_out + row * LL + kt * KT + (tk << 2)) =
                    make_float4(s[i][0], s[i][1], s[i][2], s[i][3]);
            }
        }
        __syncthreads();

        // O += P @ V
        #pragma unroll
        for (int kk = 0; kk < 64; kk++) {
            float4 v = *(const float4*)(Vs + kk * SROW + (tk << 2));
            float p0 = Ps[((tq << 2) + 0) * SROW + kk];
            float p1 = Ps[((tq << 2) + 1) * SROW + kk];
            float p2 = Ps[((tq << 2) + 2) * SROW + kk];
            float p3 = Ps[((tq << 2) + 3) * SROW + kk];
            o[0][0] += p0 * v.x; o[0][1] += p0 * v.y; o[0][2] += p0 * v.z; o[0][3] += p0 * v.w;
            o[1][0] += p1 * v.x; o[1][1] += p1 * v.y; o[1][2] += p1 * v.z; o[1][3] += p1 * v.w;
            o[2][0] += p2 * v.x; o[2][1] += p2 * v.y; o[2][2] += p2 * v.z; o[2][3] += p2 * v.w;
            o[3][0] += p3 * v.x; o[3][1] += p3 * v.y; o[3][2] += p3 * v.z; o[3][3] += p3 * v.w;
        }
        __syncthreads();
    }

    // rowsum reduce across the 16 tk lanes (they sit in one 16-lane half-warp)
    #pragma unroll
    for (int off = 8; off > 0; off >>= 1) {
        #pragma unroll
        for (int i = 0; i < 4; i++)
            rs[i] += __shfl_xor_sync(0xffffffffu, rs[i], off);
    }
    float inv[4];
    #pragma unroll
    for (int i = 0; i < 4; i++) inv[i] = 1.f / rs[i];
    if (tk == 0) {
        #pragma unroll
        for (int i = 0; i < 4; i++)
            g_inv[(size_t)bh * LL + q0 + (tq << 2) + i] = inv[i];
    }

    // store normalized O in [b][l][D] layout
    #pragma unroll
    for (int i = 0; i < 4; i++) {
        int q = q0 + (tq << 2) + i;
        *(float4*)(g_O + ((size_t)b * LL + q) * DM + h * DK + (tk << 2)) =
            make_float4(o[i][0] * inv[i], o[i][1] * inv[i],
                        o[i][2] * inv[i], o[i][3] * inv[i]);
    }
}

// ============================================================================
// normalize attn: attn[row][k] *= 1/rowsum[row]
// ============================================================================
__global__ __launch_bounds__(256) void norm_attn_kernel(float4* __restrict__ attn)
{
    int i4 = blockIdx.x * 256 + threadIdx.x;      // 0 .. 33554431
    int row = i4 >> 9;                            // (i4*4)/2048
    float inv = g_inv[row];
    float4 v = attn[i4];
    v.x *= inv; v.y *= inv; v.z *= inv; v.w *= inv;
    attn[i4] = v;
}

// ============================================================================
// output projection: out = O @ Wo^T + bo  (plain store)
// ============================================================================
__global__ __launch_bounds__(256) void out_proj_kernel(
    const float* __restrict__ Wo, const float* __restrict__ bo,
    float* __restrict__ out)
{
    __shared__ float As[8][128];
    __shared__ float Bs[8][128];

    const int bm = blockIdx.y * 128;
    const int bn = blockIdx.x * 128;
    const int tid = threadIdx.x;
    const int tr = (tid >> 4) << 3;
    const int tc = (tid & 15) << 3;
    const int lr = tid >> 1;
    const int lk = (tid & 1) << 2;

    float acc[8][8];
    #pragma unroll
    for (int i = 0; i < 8; i++)
        #pragma unroll
        for (int j = 0; j < 8; j++) acc[i][j] = 0.f;

    for (int k0 = 0; k0 < DM; k0 += 8) {
        float4 av  = *(const float4*)(g_O + (size_t)(bm + lr) * DM + k0 + lk);
        float4 bv4 = *(const float4*)(Wo  + (size_t)(bn + lr) * DM + k0 + lk);
        As[lk + 0][lr] = av.x;  As[lk + 1][lr] = av.y;
        As[lk + 2][lr] = av.z;  As[lk + 3][lr] = av.w;
        Bs[lk + 0][lr] = bv4.x; Bs[lk + 1][lr] = bv4.y;
        Bs[lk + 2][lr] = bv4.z; Bs[lk + 3][lr] = bv4.w;
        __syncthreads();
        #pragma unroll
        for (int k = 0; k < 8; k++) {
            float4 a0 = *(const float4*)(&As[k][tr]);
            float4 a1 = *(const float4*)(&As[k][tr + 4]);
            float4 b0 = *(const float4*)(&Bs[k][tc]);
            float4 b1 = *(const float4*)(&Bs[k][tc + 4]);
            float a[8] = {a0.x, a0.y, a0.z, a0.w, a1.x, a1.y, a1.z, a1.w};
            float b[8] = {b0.x, b0.y, b0.z, b0.w, b1.x, b1.y, b1.z, b1.w};
            #pragma unroll
            for (int i = 0; i < 8; i++)
                #pragma unroll
                for (int j = 0; j < 8; j++) acc[i][j] += a[i] * b[j];
        }
        __syncthreads();
    }

    #pragma unroll
    for (int i = 0; i < 8; i++) {
        int m = bm + tr + i;
        #pragma unroll
        for (int j = 0; j < 8; j++) {
            int o = bn + tc + j;
            out[(size_t)m * DM + o] = acc[i][j] + bo[o];
        }
    }
}

// ============================================================================
extern "C" void kernel_launch(void* const* d_in, const int* in_sizes, int n_in,
                              void* d_out, int out_size)
{
    const float* x    = (const float*)d_in[0];
    const int*   mask = (const int*)  d_in[1];
    const float* Wq   = (const float*)d_in[2];
    const float* bq   = (const float*)d_in[3];
    const float* Wk   = (const float*)d_in[4];
    const float* bk   = (const float*)d_in[5];
    const float* Wv   = (const float*)d_in[6];
    const float* bv   = (const float*)d_in[7];
    const float* Wo   = (const float*)d_in[8];
    const float* bo   = (const float*)d_in[9];
    float* out = (float*)d_out;

    const size_t out_elems  = (size_t)BB * LL * DM;            // 4,194,304
    const size_t attn_elems = (size_t)BB * NH * LL * LL;       // 134,217,728
    float* attn = ((size_t)out_size >= out_elems + attn_elems)
                      ? (out + out_elems) : nullptr;

    const int smem_attn = (4 * 64 * SROW) * (int)sizeof(float) + 64 * (int)sizeof(int);
    cudaFuncSetAttribute(attn_kernel,
                         cudaFuncAttributeMaxDynamicSharedMemorySize, smem_attn);

    qkv_proj_kernel<<<dim3(DM / 128, MM / 128, 3), 256>>>(x, Wq, Wk, Wv, bq, bk, bv);
    attn_kernel<<<dim3(LL / QT, BB * NH), 256, smem_attn>>>(mask, attn);
    if (attn) {
        norm_attn_kernel<<<(int)(attn_elems / 4 / 256), 256>>>((float4*)attn);
    }
    out_proj_kernel<<<dim3(DM / 128, MM / 128), 256>>>(Wo, bo, out);
}

// round 4
// speedup vs baseline: 2.0941x; 2.0941x over previous
#include <cuda_runtime.h>
#include <cuda_bf16.h>
#include <cstdint>

#define BB 2
#define LL 2048
#define DM 1024
#define NH 16
#define MM (BB*LL)

// ---------------- device scratch (bf16 hi/lo pairs) -------------------------
__device__ __align__(16) __nv_bfloat16 g_xh[MM*DM], g_xl[MM*DM];
__device__ __align__(16) __nv_bfloat16 g_wh[4][DM*DM], g_wl[4][DM*DM];  // Wq,Wk,Wv,Wo
__device__ __align__(16) __nv_bfloat16 g_Qh[MM*DM], g_Ql[MM*DM];        // [bh][l][64], pre-scaled 1/8
__device__ __align__(16) __nv_bfloat16 g_Kh[MM*DM], g_Kl[MM*DM];        // [bh][l][64]
__device__ __align__(16) __nv_bfloat16 g_Vh[MM*DM], g_Vl[MM*DM];        // transposed [bh][d][l]
__device__ __align__(16) __nv_bfloat16 g_Oh[MM*DM], g_Ol[MM*DM];        // [b][l][1024]
__device__ float g_inv[BB*NH*LL];

// ---------------- mma helpers ------------------------------------------------
__device__ __forceinline__ void mma16816(float* c, const uint32_t* a, const uint32_t* b){
    asm volatile("mma.sync.aligned.m16n8k16.row.col.f32.bf16.bf16.f32 "
        "{%0,%1,%2,%3}, {%4,%5,%6,%7}, {%8,%9}, {%0,%1,%2,%3};"
        : "+f"(c[0]), "+f"(c[1]), "+f"(c[2]), "+f"(c[3])
        : "r"(a[0]), "r"(a[1]), "r"(a[2]), "r"(a[3]), "r"(b[0]), "r"(b[1]));
}
// A fragment m16k16 (row-major source), row stride S elems
__device__ __forceinline__ void ldA(uint32_t* a, const __nv_bfloat16* s, int S, int m0, int k0, int lane){
    int r = lane >> 2, c = lane & 3;
    const __nv_bfloat16* p = s + (size_t)(m0 + r) * S + k0 + 2 * c;
    a[0] = *(const uint32_t*)p;
    a[1] = *(const uint32_t*)(p + 8 * S);
    a[2] = *(const uint32_t*)(p + 8);
    a[3] = *(const uint32_t*)(p + 8 * S + 8);
}
// B fragment n8k16 from B^T stored row-major [n][k], row stride S elems
__device__ __forceinline__ void ldB(uint32_t* b, const __nv_bfloat16* s, int S, int n0, int k0, int lane){
    int r = lane >> 2, c = lane & 3;
    const __nv_bfloat16* p = s + (size_t)(n0 + r) * S + k0 + 2 * c;
    b[0] = *(const uint32_t*)p;
    b[1] = *(const uint32_t*)(p + 8);
}
__device__ __forceinline__ void split_bf(float v, __nv_bfloat16& h, __nv_bfloat16& l){
    h = __float2bfloat16(v);
    l = __float2bfloat16(v - __bfloat162float(h));
}
__device__ __forceinline__ uint32_t pack2(float v0, float v1){
    __nv_bfloat162 t = __floats2bfloat162_rn(0.f, 0.f);
    __nv_bfloat16 a = __float2bfloat16(v0), b = __float2bfloat16(v1);
    t = __halves2bfloat162(a, b);
    return *(uint32_t*)&t;
}

// ============================================================================
// fp32 -> hi/lo bf16 conversion
// ============================================================================
__global__ __launch_bounds__(256) void cvt_kernel(const float* __restrict__ s, int target){
    __nv_bfloat16 *dh, *dl; int n;
    if (target == 0) { dh = g_xh; dl = g_xl; n = MM*DM; }
    else             { dh = g_wh[target-1]; dl = g_wl[target-1]; n = DM*DM; }
    int i = blockIdx.x * 256 + threadIdx.x;
    if (i < n) {
        float v = s[i];
        __nv_bfloat16 h, l; split_bf(v, h, l);
        dh[i] = h; dl[i] = l;
    }
}

// ============================================================================
// projection GEMM: C = A @ B^T + bias, 3-MMA hi/lo split.
// mode 0:Q 1:K 2:V 3:OUT. Block 128x128, 8 warps (2x4), warp tile 64x32.
// ============================================================================
#define SA 40   // smem row stride (32 + 8 pad)
__global__ __launch_bounds__(256, 1) void proj_kernel(const float* __restrict__ bias,
                                                      float* __restrict__ fout, int mode){
    extern __shared__ char smraw[];
    __nv_bfloat16* S = (__nv_bfloat16*)smraw;
    __nv_bfloat16 *Ah = S, *Al = S + 5120, *Bh = S + 10240, *Bl = S + 15360;
    __shared__ float s_bias[128];

    const __nv_bfloat16* gAh = (mode < 3) ? g_xh : g_Oh;
    const __nv_bfloat16* gAl = (mode < 3) ? g_xl : g_Ol;
    const __nv_bfloat16* gBh = g_wh[mode];
    const __nv_bfloat16* gBl = g_wl[mode];

    const int bm = blockIdx.y * 128, bn = blockIdx.x * 128;
    const int tid = threadIdx.x, w = tid >> 5, lane = tid & 31;
    const int wm = w >> 2, wn = w & 3;
    if (tid < 128) s_bias[tid] = bias[bn + tid];

    float C[4][4][4];
    #pragma unroll
    for (int i = 0; i < 4; i++)
        #pragma unroll
        for (int j = 0; j < 4; j++)
            #pragma unroll
            for (int q = 0; q < 4; q++) C[i][j][q] = 0.f;

    for (int k0 = 0; k0 < DM; k0 += 32) {
        __syncthreads();
        #pragma unroll
        for (int i = tid; i < 2048; i += 256) {
            int t = i >> 9, e = i & 511, r = e >> 2, c4 = e & 3;
            const __nv_bfloat16* src = (t==0)?gAh:(t==1)?gAl:(t==2)?gBh:gBl;
            __nv_bfloat16* dst = (t==0)?Ah:(t==1)?Al:(t==2)?Bh:Bl;
            int rowbase = (t < 2) ? bm : bn;
            *(uint4*)(dst + r * SA + c4 * 8) =
                *(const uint4*)(src + (size_t)(rowbase + r) * DM + k0 + c4 * 8);
        }
        __syncthreads();
        #pragma unroll
        for (int ks = 0; ks < 2; ks++) {
            uint32_t fbh[4][2], fbl[4][2];
            #pragma unroll
            for (int nt = 0; nt < 4; nt++) {
                ldB(fbh[nt], Bh, SA, wn * 32 + nt * 8, ks * 16, lane);
                ldB(fbl[nt], Bl, SA, wn * 32 + nt * 8, ks * 16, lane);
            }
            #pragma unroll
            for (int mt = 0; mt < 4; mt++) {
                uint32_t fah[4], fal[4];
                ldA(fah, Ah, SA, wm * 64 + mt * 16, ks * 16, lane);
                ldA(fal, Al, SA, wm * 64 + mt * 16, ks * 16, lane);
                #pragma unroll
                for (int nt = 0; nt < 4; nt++) {
                    mma16816(C[mt][nt], fah, fbh[nt]);
                    mma16816(C[mt][nt], fah, fbl[nt]);
                    mma16816(C[mt][nt], fal, fbh[nt]);
                }
            }
        }
    }

    // epilogue
    const int r = lane >> 2, cq = lane & 3;
    const float scl = (mode == 0) ? 0.125f : 1.0f;
    #pragma unroll
    for (int mt = 0; mt < 4; mt++) {
        #pragma unroll
        for (int nt = 0; nt < 4; nt++) {
            int nloc = wn * 32 + nt * 8 + 2 * cq;
            int n = bn + nloc;
            #pragma unroll
            for (int hf = 0; hf < 2; hf++) {
                int m = bm + wm * 64 + mt * 16 + r + hf * 8;
                float v0 = (C[mt][nt][hf*2+0] + s_bias[nloc])     * scl;
                float v1 = (C[mt][nt][hf*2+1] + s_bias[nloc + 1]) * scl;
                if (mode == 3) {
                    *(float2*)(fout + (size_t)m * DM + n) = make_float2(v0, v1);
                } else {
                    int bidx = m >> 11, l = m & 2047, h = n >> 6, d = n & 63;
                    __nv_bfloat16 h0,l0,h1,l1; split_bf(v0,h0,l0); split_bf(v1,h1,l1);
                    if (mode < 2) {
                        __nv_bfloat16* DH = mode == 0 ? g_Qh : g_Kh;
                        __nv_bfloat16* DL = mode == 0 ? g_Ql : g_Kl;
                        size_t idx = (((size_t)bidx * NH + h) * LL + l) * 64 + d;
                        *(__nv_bfloat162*)(DH + idx) = __halves2bfloat162(h0, h1);
                        *(__nv_bfloat162*)(DL + idx) = __halves2bfloat162(l0, l1);
                    } else {
                        size_t idx = (((size_t)bidx * NH + h) * 64 + d) * LL + l;
                        g_Vh[idx] = h0; g_Vl[idx] = l0;
                        g_Vh[idx + LL] = h1; g_Vl[idx + LL] = l1;
                    }
                }
            }
        }
    }
}

// ============================================================================
// fused attention: per (bh, 128-q tile). Single pass over K tiles of 128.
// S = (Q/8)K^T via mma; e = exp(S)*mask -> unnormalized attn write + P smem;
// O += P V via mma; rowsums in regs; O scaled by 1/rowsum at end.
// 8 warps: wq = w>>2 (q half), wn/wd = w&3.
// ============================================================================
#define SQ 72    // Q/K row stride (64 + 8)
#define SV 136   // V/P row stride (128 + 8)
__global__ __launch_bounds__(256, 1) void attn_kernel(const int* __restrict__ mask,
                                                      float* __restrict__ attn){
    extern __shared__ char smraw[];
    __nv_bfloat16* S = (__nv_bfloat16*)smraw;
    __nv_bfloat16 *Qh = S,           *Ql = S + 9216,
                  *Kh = S + 18432,   *Kl = S + 27648,
                  *Vh = S + 36864,   *Vl = S + 45568,
                  *Ph = S + 54272,   *Pl = S + 71680;
    __shared__ float s_msk[128];
    __shared__ float s_rs[128][4];
    __shared__ float s_inv[128];

    const int bh = blockIdx.y, q0 = blockIdx.x * 128, b = bh >> 4;
    const int tid = threadIdx.x, w = tid >> 5, lane = tid & 31;
    const int wq = w >> 2, wn = w & 3;
    const int r = lane >> 2, cq = lane & 3;

    // persistent Q tile [128][64] hi/lo
    #pragma unroll
    for (int i = tid; i < 2048; i += 256) {
        int t = i >> 10, e = i & 1023, rr = e >> 3, c8 = e & 7;
        const __nv_bfloat16* src = (t ? g_Ql : g_Qh) + ((size_t)bh * LL + q0) * 64;
        __nv_bfloat16* dst = t ? Ql : Qh;
        *(uint4*)(dst + rr * SQ + c8 * 8) = *(const uint4*)(src + (size_t)rr * 64 + c8 * 8);
    }

    float O[4][2][4];
    #pragma unroll
    for (int i=0;i<4;i++) for (int j=0;j<2;j++) for (int q=0;q<4;q++) O[i][j][q]=0.f;
    float rs[4][2] = {{0,0},{0,0},{0,0},{0,0}};

    for (int kt = 0; kt < 16; kt++) {
        const int k0g = kt * 128;
        __syncthreads();
        // K tile [128][64] hi/lo
        #pragma unroll
        for (int i = tid; i < 2048; i += 256) {
            int t = i >> 10, e = i & 1023, rr = e >> 3, c8 = e & 7;
            const __nv_bfloat16* src = (t ? g_Kl : g_Kh) + ((size_t)bh * LL + k0g) * 64;
            __nv_bfloat16* dst = t ? Kl : Kh;
            *(uint4*)(dst + rr * SQ + c8 * 8) = *(const uint4*)(src + (size_t)rr * 64 + c8 * 8);
        }
        // V tile [64 d][128 k] hi/lo (from transposed g_V)
        #pragma unroll
        for (int i = tid; i < 2048; i += 256) {
            int t = i >> 10, e = i & 1023, rr = e >> 4, c8 = e & 15;
            const __nv_bfloat16* src = (t ? g_Vl : g_Vh) + (size_t)bh * 64 * LL;
            __nv_bfloat16* dst = t ? Vl : Vh;
            *(uint4*)(dst + rr * SV + c8 * 8) =
                *(const uint4*)(src + (size_t)rr * LL + k0g + c8 * 8);
        }
        if (tid < 128) s_msk[tid] = mask[b * LL + k0g + tid] ? 1.f : 0.f;
        __syncthreads();

        // ---- S = Q K^T ----
        float Cs[4][4][4];
        #pragma unroll
        for (int i=0;i<4;i++) for (int j=0;j<4;j++) for (int q=0;q<4;q++) Cs[i][j][q]=0.f;
        #pragma unroll
        for (int ks = 0; ks < 4; ks++) {
            uint32_t fbh[4][2], fbl[4][2];
            #pragma unroll
            for (int nt = 0; nt < 4; nt++) {
                ldB(fbh[nt], Kh, SQ, wn * 32 + nt * 8, ks * 16, lane);
                ldB(fbl[nt], Kl, SQ, wn * 32 + nt * 8, ks * 16, lane);
            }
            #pragma unroll
            for (int mt = 0; mt < 4; mt++) {
                uint32_t fah[4], fal[4];
                ldA(fah, Qh, SQ, wq * 64 + mt * 16, ks * 16, lane);
                ldA(fal, Ql, SQ, wq * 64 + mt * 16, ks * 16, lane);
                #pragma unroll
                for (int nt = 0; nt < 4; nt++) {
                    mma16816(Cs[mt][nt], fah, fbh[nt]);
                    mma16816(Cs[mt][nt], fah, fbl[nt]);
                    mma16816(Cs[mt][nt], fal, fbh[nt]);
                }
            }
        }

        // ---- e = exp(S)*mask: attn write, rowsum, P smem ----
        #pragma unroll
        for (int mt = 0; mt < 4; mt++) {
            #pragma unroll
            for (int nt = 0; nt < 4; nt++) {
                int col = wn * 32 + nt * 8 + 2 * cq;
                float m0 = s_msk[col], m1 = s_msk[col + 1];
                #pragma unroll
                for (int hf = 0; hf < 2; hf++) {
                    int row = wq * 64 + mt * 16 + r + hf * 8;
                    float e0 = __expf(Cs[mt][nt][hf*2+0]) * m0;
                    float e1 = __expf(Cs[mt][nt][hf*2+1]) * m1;
                    rs[mt][hf] += e0 + e1;
                    if (attn)
                        *(float2*)(attn + ((size_t)bh * LL + q0 + row) * LL + k0g + col) =
                            make_float2(e0, e1);
                    __nv_bfloat16 h0,l0,h1,l1; split_bf(e0,h0,l0); split_bf(e1,h1,l1);
                    *(__nv_bfloat162*)(Ph + (size_t)row * SV + col) = __halves2bfloat162(h0,h1);
                    *(__nv_bfloat162*)(Pl + (size_t)row * SV + col) = __halves2bfloat162(l0,l1);
                }
            }
        }
        __syncthreads();

        // ---- O += P V ----  (wd = wn: d range 16 per warp)
        #pragma unroll
        for (int ks = 0; ks < 8; ks++) {
            uint32_t vbh[2][2], vbl[2][2];
            #pragma unroll
            for (int nt = 0; nt < 2; nt++) {
                ldB(vbh[nt], Vh, SV, wn * 16 + nt * 8, ks * 16, lane);
                ldB(vbl[nt], Vl, SV, wn * 16 + nt * 8, ks * 16, lane);
            }
            #pragma unroll
            for (int mt = 0; mt < 4; mt++) {
                uint32_t pah[4], pal[4];
                ldA(pah, Ph, SV, wq * 64 + mt * 16, ks * 16, lane);
                ldA(pal, Pl, SV, wq * 64 + mt * 16, ks * 16, lane);
                #pragma unroll
                for (int nt = 0; nt < 2; nt++) {
                    mma16816(O[mt][nt], pah, vbh[nt]);
                    mma16816(O[mt][nt], pah, vbl[nt]);
                    mma16816(O[mt][nt], pal, vbh[nt]);
                }
            }
        }
    }

    // ---- rowsum reduce ----
    #pragma unroll
    for (int mt = 0; mt < 4; mt++)
        #pragma unroll
        for (int hf = 0; hf < 2; hf++) {
            rs[mt][hf] += __shfl_xor_sync(0xffffffffu, rs[mt][hf], 1);
            rs[mt][hf] += __shfl_xor_sync(0xffffffffu, rs[mt][hf], 2);
        }
    if (cq == 0) {
        #pragma unroll
        for (int mt = 0; mt < 4; mt++)
            #pragma unroll
            for (int hf = 0; hf < 2; hf++)
                s_rs[wq * 64 + mt * 16 + r + hf * 8][wn] = rs[mt][hf];
    }
    __syncthreads();
    if (tid < 128) {
        float s = s_rs[tid][0] + s_rs[tid][1] + s_rs[tid][2] + s_rs[tid][3];
        float iv = 1.f / s;
        s_inv[tid] = iv;
        g_inv[(size_t)bh * LL + q0 + tid] = iv;
    }
    __syncthreads();

    // ---- O epilogue ----
    #pragma unroll
    for (int mt = 0; mt < 4; mt++) {
        #pragma unroll
        for (int nt = 0; nt < 2; nt++) {
            int d = wn * 16 + nt * 8 + 2 * cq;
            #pragma unroll
            for (int hf = 0; hf < 2; hf++) {
                int row = wq * 64 + mt * 16 + r + hf * 8;
                float iv = s_inv[row];
                float v0 = O[mt][nt][hf*2+0] * iv;
                float v1 = O[mt][nt][hf*2+1] * iv;
                __nv_bfloat16 h0,l0,h1,l1; split_bf(v0,h0,l0); split_bf(v1,h1,l1);
                size_t idx = ((size_t)b * LL + q0 + row) * DM + (bh & 15) * 64 + d;
                *(__nv_bfloat162*)(g_Oh + idx) = __halves2bfloat162(h0, h1);
                *(__nv_bfloat162*)(g_Ol + idx) = __halves2bfloat162(l0, l1);
            }
        }
    }
}

// ============================================================================
// normalize attn rows by 1/rowsum
// ============================================================================
__global__ __launch_bounds__(256) void norm_attn_kernel(float4* __restrict__ attn){
    int i4 = blockIdx.x * 256 + threadIdx.x;
    int row = i4 >> 9;
    float inv = g_inv[row];
    float4 v = attn[i4];
    v.x *= inv; v.y *= inv; v.z *= inv; v.w *= inv;
    attn[i4] = v;
}

// ============================================================================
extern "C" void kernel_launch(void* const* d_in, const int* in_sizes, int n_in,
                              void* d_out, int out_size)
{
    const float* x    = (const float*)d_in[0];
    const int*   mask = (const int*)  d_in[1];
    const float* bq   = (const float*)d_in[3];
    const float* bk   = (const float*)d_in[5];
    const float* bv   = (const float*)d_in[7];
    const float* bo   = (const float*)d_in[9];
    float* out = (float*)d_out;

    const size_t out_elems  = (size_t)MM * DM;
    const size_t attn_elems = (size_t)BB * NH * LL * LL;
    float* attn = ((size_t)out_size >= out_elems + attn_elems) ? (out + out_elems) : nullptr;

    const int smem_proj = 20480 * 2;
    const int smem_attn = 89088 * 2;
    cudaFuncSetAttribute(proj_kernel, cudaFuncAttributeMaxDynamicSharedMemorySize, smem_proj);
    cudaFuncSetAttribute(attn_kernel, cudaFuncAttributeMaxDynamicSharedMemorySize, smem_attn);

    cvt_kernel<<<(MM*DM + 255)/256, 256>>>(x, 0);
    cvt_kernel<<<(DM*DM + 255)/256, 256>>>((const float*)d_in[2], 1);
    cvt_kernel<<<(DM*DM + 255)/256, 256>>>((const float*)d_in[4], 2);
    cvt_kernel<<<(DM*DM + 255)/256, 256>>>((const float*)d_in[6], 3);
    cvt_kernel<<<(DM*DM + 255)/256, 256>>>((const float*)d_in[8], 4);

    proj_kernel<<<dim3(8, 32), 256, smem_proj>>>(bq, nullptr, 0);
    proj_kernel<<<dim3(8, 32), 256, smem_proj>>>(bk, nullptr, 1);
    proj_kernel<<<dim3(8, 32), 256, smem_proj>>>(bv, nullptr, 2);

    attn_kernel<<<dim3(LL / 128, BB * NH), 256, smem_attn>>>(mask, attn);
    if (attn)
        norm_attn_kernel<<<(int)(attn_elems / 4 / 256), 256>>>((float4*)attn);

    proj_kernel<<<dim3(8, 32), 256, smem_proj>>>(bo, out, 3);
}

// round 5
// speedup vs baseline: 2.1728x; 1.0376x over previous
#include <cuda_runtime.h>
#include <cuda_bf16.h>
#include <cstdint>

#define BB 2
#define LL 2048
#define DM 1024
#define NH 16
#define MM (BB*LL)

// ---------------- device scratch (bf16 hi/lo pairs) -------------------------
__device__ __align__(16) __nv_bfloat16 g_xh[MM*DM], g_xl[MM*DM];
__device__ __align__(16) __nv_bfloat16 g_wh[4][DM*DM], g_wl[4][DM*DM];  // Wq,Wk,Wv,Wo
__device__ __align__(16) __nv_bfloat16 g_Qh[MM*DM], g_Ql[MM*DM];        // [bh][l][64], pre-scaled 1/8
__device__ __align__(16) __nv_bfloat16 g_Kh[MM*DM], g_Kl[MM*DM];        // [bh][l][64]
__device__ __align__(16) __nv_bfloat16 g_Vh[MM*DM], g_Vl[MM*DM];        // transposed [bh][d][l]
__device__ __align__(16) __nv_bfloat16 g_Oh[MM*DM], g_Ol[MM*DM];        // [b][l][1024]

// ---------------- mma helpers ------------------------------------------------
__device__ __forceinline__ void mma16816(float* c, const uint32_t* a, const uint32_t* b){
    asm volatile("mma.sync.aligned.m16n8k16.row.col.f32.bf16.bf16.f32 "
        "{%0,%1,%2,%3}, {%4,%5,%6,%7}, {%8,%9}, {%0,%1,%2,%3};"
        : "+f"(c[0]), "+f"(c[1]), "+f"(c[2]), "+f"(c[3])
        : "r"(a[0]), "r"(a[1]), "r"(a[2]), "r"(a[3]), "r"(b[0]), "r"(b[1]));
}
__device__ __forceinline__ void ldA(uint32_t* a, const __nv_bfloat16* s, int S, int m0, int k0, int lane){
    int r = lane >> 2, c = lane & 3;
    const __nv_bfloat16* p = s + (size_t)(m0 + r) * S + k0 + 2 * c;
    a[0] = *(const uint32_t*)p;
    a[1] = *(const uint32_t*)(p + 8 * S);
    a[2] = *(const uint32_t*)(p + 8);
    a[3] = *(const uint32_t*)(p + 8 * S + 8);
}
__device__ __forceinline__ void ldB(uint32_t* b, const __nv_bfloat16* s, int S, int n0, int k0, int lane){
    int r = lane >> 2, c = lane & 3;
    const __nv_bfloat16* p = s + (size_t)(n0 + r) * S + k0 + 2 * c;
    b[0] = *(const uint32_t*)p;
    b[1] = *(const uint32_t*)(p + 8);
}
__device__ __forceinline__ void split_bf(float v, __nv_bfloat16& h, __nv_bfloat16& l){
    h = __float2bfloat16(v);
    l = __float2bfloat16(v - __bfloat162float(h));
}

// ============================================================================
// fp32 -> hi/lo bf16 conversion, all tensors in one launch
// ============================================================================
__global__ __launch_bounds__(256) void cvt_all_kernel(
    const float* __restrict__ x,  const float* __restrict__ wq,
    const float* __restrict__ wk, const float* __restrict__ wv,
    const float* __restrict__ wo)
{
    size_t i = (size_t)blockIdx.x * 256 + threadIdx.x;   // 0 .. 8M-1
    const float* s; __nv_bfloat16 *dh, *dl; size_t off;
    if (i < (size_t)MM * DM) {
        s = x; dh = g_xh; dl = g_xl; off = i;
    } else {
        size_t j = i - (size_t)MM * DM;
        int t = (int)(j >> 20);               // DM*DM = 2^20
        off = j & ((1u << 20) - 1);
        s = (t == 0) ? wq : (t == 1) ? wk : (t == 2) ? wv : wo;
        dh = g_wh[t]; dl = g_wl[t];
    }
    float v = s[off];
    __nv_bfloat16 h, l; split_bf(v, h, l);
    dh[off] = h; dl[off] = l;
}

// ============================================================================
// projection GEMM: C = A @ B^T + bias, 3-MMA hi/lo split.
// mode_arg -1: mode = blockIdx.z in {0:Q,1:K,2:V}; mode_arg 3: out proj.
// Block 128x128, 8 warps (2x4), warp tile 64x32.
// ============================================================================
#define SA 40
__global__ __launch_bounds__(256, 1) void proj_kernel(
    const float* __restrict__ b0, const float* __restrict__ b1,
    const float* __restrict__ b2, float* __restrict__ fout, int mode_arg)
{
    extern __shared__ char smraw[];
    __nv_bfloat16* S = (__nv_bfloat16*)smraw;
    __nv_bfloat16 *Ah = S, *Al = S + 5120, *Bh = S + 10240, *Bl = S + 15360;
    __shared__ float s_bias[128];

    const int mode = (mode_arg < 0) ? (int)blockIdx.z : mode_arg;
    const float* bias = (mode == 1) ? b1 : (mode == 2) ? b2 : b0;
    const __nv_bfloat16* gAh = (mode < 3) ? g_xh : g_Oh;
    const __nv_bfloat16* gAl = (mode < 3) ? g_xl : g_Ol;
    const __nv_bfloat16* gBh = g_wh[mode];
    const __nv_bfloat16* gBl = g_wl[mode];

    const int bm = blockIdx.y * 128, bn = blockIdx.x * 128;
    const int tid = threadIdx.x, w = tid >> 5, lane = tid & 31;
    const int wm = w >> 2, wn = w & 3;
    if (tid < 128) s_bias[tid] = bias[bn + tid];

    float C[4][4][4];
    #pragma unroll
    for (int i = 0; i < 4; i++)
        #pragma unroll
        for (int j = 0; j < 4; j++)
            #pragma unroll
            for (int q = 0; q < 4; q++) C[i][j][q] = 0.f;

    for (int k0 = 0; k0 < DM; k0 += 32) {
        __syncthreads();
        #pragma unroll
        for (int i = tid; i < 2048; i += 256) {
            int t = i >> 9, e = i & 511, r = e >> 2, c4 = e & 3;
            const __nv_bfloat16* src = (t==0)?gAh:(t==1)?gAl:(t==2)?gBh:gBl;
            __nv_bfloat16* dst = (t==0)?Ah:(t==1)?Al:(t==2)?Bh:Bl;
            int rowbase = (t < 2) ? bm : bn;
            *(uint4*)(dst + r * SA + c4 * 8) =
                *(const uint4*)(src + (size_t)(rowbase + r) * DM + k0 + c4 * 8);
        }
        __syncthreads();
        #pragma unroll
        for (int ks = 0; ks < 2; ks++) {
            uint32_t fbh[4][2], fbl[4][2];
            #pragma unroll
            for (int nt = 0; nt < 4; nt++) {
                ldB(fbh[nt], Bh, SA, wn * 32 + nt * 8, ks * 16, lane);
                ldB(fbl[nt], Bl, SA, wn * 32 + nt * 8, ks * 16, lane);
            }
            #pragma unroll
            for (int mt = 0; mt < 4; mt++) {
                uint32_t fah[4], fal[4];
                ldA(fah, Ah, SA, wm * 64 + mt * 16, ks * 16, lane);
                ldA(fal, Al, SA, wm * 64 + mt * 16, ks * 16, lane);
                #pragma unroll
                for (int nt = 0; nt < 4; nt++) {
                    mma16816(C[mt][nt], fah, fbh[nt]);
                    mma16816(C[mt][nt], fah, fbl[nt]);
                    mma16816(C[mt][nt], fal, fbh[nt]);
                }
            }
        }
    }

    const int r = lane >> 2, cq = lane & 3;
    const float scl = (mode == 0) ? 0.125f : 1.0f;
    #pragma unroll
    for (int mt = 0; mt < 4; mt++) {
        #pragma unroll
        for (int nt = 0; nt < 4; nt++) {
            int nloc = wn * 32 + nt * 8 + 2 * cq;
            int n = bn + nloc;
            #pragma unroll
            for (int hf = 0; hf < 2; hf++) {
                int m = bm + wm * 64 + mt * 16 + r + hf * 8;
                float v0 = (C[mt][nt][hf*2+0] + s_bias[nloc])     * scl;
                float v1 = (C[mt][nt][hf*2+1] + s_bias[nloc + 1]) * scl;
                if (mode == 3) {
                    *(float2*)(fout + (size_t)m * DM + n) = make_float2(v0, v1);
                } else {
                    int bidx = m >> 11, l = m & 2047, h = n >> 6, d = n & 63;
                    __nv_bfloat16 h0,l0,h1,l1; split_bf(v0,h0,l0); split_bf(v1,h1,l1);
                    if (mode < 2) {
                        __nv_bfloat16* DH = mode == 0 ? g_Qh : g_Kh;
                        __nv_bfloat16* DL = mode == 0 ? g_Ql : g_Kl;
                        size_t idx = (((size_t)bidx * NH + h) * LL + l) * 64 + d;
                        *(__nv_bfloat162*)(DH + idx) = __halves2bfloat162(h0, h1);
                        *(__nv_bfloat162*)(DL + idx) = __halves2bfloat162(l0, l1);
                    } else {
                        size_t idx = (((size_t)bidx * NH + h) * 64 + d) * LL + l;
                        g_Vh[idx] = h0; g_Vl[idx] = l0;
                        g_Vh[idx + LL] = h1; g_Vl[idx + LL] = l1;
                    }
                }
            }
        }
    }
}

// ============================================================================
// fused attention, TWO PASS. per (bh, 128-q tile):
// pass1: S = QK^T (2-MMA: Qh.Kh + Ql.Kh), rowsums only -> inv per row.
// pass2: S (3-MMA), e = exp*mask*inv -> NORMALIZED attn write + P smem,
//        O += P V (3-MMA). No norm kernel, no final O scale.
// ============================================================================
#define SQ 72
#define SV 136
__global__ __launch_bounds__(256, 1) void attn_kernel(const int* __restrict__ mask,
                                                      float* __restrict__ attn){
    extern __shared__ char smraw[];
    __nv_bfloat16* S = (__nv_bfloat16*)smraw;
    __nv_bfloat16 *Qh = S,           *Ql = S + 9216,
                  *Kh = S + 18432,   *Kl = S + 27648,
                  *Vh = S + 36864,   *Vl = S + 45568,
                  *Ph = S + 54272,   *Pl = S + 71680;
    __shared__ float s_msk[128];
    __shared__ float s_rs[128][4];
    __shared__ float s_inv[128];

    const int bh = blockIdx.y, q0 = blockIdx.x * 128, b = bh >> 4;
    const int tid = threadIdx.x, w = tid >> 5, lane = tid & 31;
    const int wq = w >> 2, wn = w & 3;
    const int r = lane >> 2, cq = lane & 3;

    // persistent Q tile [128][64] hi/lo
    #pragma unroll
    for (int i = tid; i < 2048; i += 256) {
        int t = i >> 10, e = i & 1023, rr = e >> 3, c8 = e & 7;
        const __nv_bfloat16* src = (t ? g_Ql : g_Qh) + ((size_t)bh * LL + q0) * 64;
        __nv_bfloat16* dst = t ? Ql : Qh;
        *(uint4*)(dst + rr * SQ + c8 * 8) = *(const uint4*)(src + (size_t)rr * 64 + c8 * 8);
    }

    float rs[4][2] = {{0,0},{0,0},{0,0},{0,0}};

    // ---------------- pass 1: rowsums ----------------
    for (int kt = 0; kt < 16; kt++) {
        const int k0g = kt * 128;
        __syncthreads();
        #pragma unroll
        for (int i = tid; i < 1024; i += 256) {
            int rr = i >> 3, c8 = i & 7;
            const __nv_bfloat16* src = g_Kh + ((size_t)bh * LL + k0g) * 64;
            *(uint4*)(Kh + rr * SQ + c8 * 8) = *(const uint4*)(src + (size_t)rr * 64 + c8 * 8);
        }
        if (tid < 128) s_msk[tid] = mask[b * LL + k0g + tid] ? 1.f : 0.f;
        __syncthreads();

        float Cs[4][4][4];
        #pragma unroll
        for (int i=0;i<4;i++) for (int j=0;j<4;j++) for (int q=0;q<4;q++) Cs[i][j][q]=0.f;
        #pragma unroll
        for (int ks = 0; ks < 4; ks++) {
            uint32_t fbh[4][2];
            #pragma unroll
            for (int nt = 0; nt < 4; nt++)
                ldB(fbh[nt], Kh, SQ, wn * 32 + nt * 8, ks * 16, lane);
            #pragma unroll
            for (int mt = 0; mt < 4; mt++) {
                uint32_t fah[4], fal[4];
                ldA(fah, Qh, SQ, wq * 64 + mt * 16, ks * 16, lane);
                ldA(fal, Ql, SQ, wq * 64 + mt * 16, ks * 16, lane);
                #pragma unroll
                for (int nt = 0; nt < 4; nt++) {
                    mma16816(Cs[mt][nt], fah, fbh[nt]);
                    mma16816(Cs[mt][nt], fal, fbh[nt]);
                }
            }
        }
        #pragma unroll
        for (int mt = 0; mt < 4; mt++)
            #pragma unroll
            for (int nt = 0; nt < 4; nt++) {
                int col = wn * 32 + nt * 8 + 2 * cq;
                float m0 = s_msk[col], m1 = s_msk[col + 1];
                #pragma unroll
                for (int hf = 0; hf < 2; hf++)
                    rs[mt][hf] += __expf(Cs[mt][nt][hf*2+0]) * m0
                                + __expf(Cs[mt][nt][hf*2+1]) * m1;
            }
    }

    // reduce rowsums -> s_inv
    #pragma unroll
    for (int mt = 0; mt < 4; mt++)
        #pragma unroll
        for (int hf = 0; hf < 2; hf++) {
            rs[mt][hf] += __shfl_xor_sync(0xffffffffu, rs[mt][hf], 1);
            rs[mt][hf] += __shfl_xor_sync(0xffffffffu, rs[mt][hf], 2);
        }
    __syncthreads();
    if (cq == 0) {
        #pragma unroll
        for (int mt = 0; mt < 4; mt++)
            #pragma unroll
            for (int hf = 0; hf < 2; hf++)
                s_rs[wq * 64 + mt * 16 + r + hf * 8][wn] = rs[mt][hf];
    }
    __syncthreads();
    if (tid < 128)
        s_inv[tid] = 1.f / (s_rs[tid][0] + s_rs[tid][1] + s_rs[tid][2] + s_rs[tid][3]);
    __syncthreads();

    float O[4][2][4];
    #pragma unroll
    for (int i=0;i<4;i++) for (int j=0;j<2;j++) for (int q=0;q<4;q++) O[i][j][q]=0.f;
    float inv_r[4][2];
    #pragma unroll
    for (int mt = 0; mt < 4; mt++)
        #pragma unroll
        for (int hf = 0; hf < 2; hf++)
            inv_r[mt][hf] = s_inv[wq * 64 + mt * 16 + r + hf * 8];

    // ---------------- pass 2: normalized attn + O ----------------
    for (int kt = 0; kt < 16; kt++) {
        const int k0g = kt * 128;
        __syncthreads();
        #pragma unroll
        for (int i = tid; i < 2048; i += 256) {
            int t = i >> 10, e = i & 1023, rr = e >> 3, c8 = e & 7;
            const __nv_bfloat16* src = (t ? g_Kl : g_Kh) + ((size_t)bh * LL + k0g) * 64;
            __nv_bfloat16* dst = t ? Kl : Kh;
            *(uint4*)(dst + rr * SQ + c8 * 8) = *(const uint4*)(src + (size_t)rr * 64 + c8 * 8);
        }
        #pragma unroll
        for (int i = tid; i < 2048; i += 256) {
            int t = i >> 10, e = i & 1023, rr = e >> 4, c8 = e & 15;
            const __nv_bfloat16* src = (t ? g_Vl : g_Vh) + (size_t)bh * 64 * LL;
            __nv_bfloat16* dst = t ? Vl : Vh;
            *(uint4*)(dst + rr * SV + c8 * 8) =
                *(const uint4*)(src + (size_t)rr * LL + k0g + c8 * 8);
        }
        if (tid < 128) s_msk[tid] = mask[b * LL + k0g + tid] ? 1.f : 0.f;
        __syncthreads();

        float Cs[4][4][4];
        #pragma unroll
        for (int i=0;i<4;i++) for (int j=0;j<4;j++) for (int q=0;q<4;q++) Cs[i][j][q]=0.f;
        #pragma unroll
        for (int ks = 0; ks < 4; ks++) {
            uint32_t fbh[4][2], fbl[4][2];
            #pragma unroll
            for (int nt = 0; nt < 4; nt++) {
                ldB(fbh[nt], Kh, SQ, wn * 32 + nt * 8, ks * 16, lane);
                ldB(fbl[nt], Kl, SQ, wn * 32 + nt * 8, ks * 16, lane);
            }
            #pragma unroll
            for (int mt = 0; mt < 4; mt++) {
                uint32_t fah[4], fal[4];
                ldA(fah, Qh, SQ, wq * 64 + mt * 16, ks * 16, lane);
                ldA(fal, Ql, SQ, wq * 64 + mt * 16, ks * 16, lane);
                #pragma unroll
                for (int nt = 0; nt < 4; nt++) {
                    mma16816(Cs[mt][nt], fah, fbh[nt]);
                    mma16816(Cs[mt][nt], fah, fbl[nt]);
                    mma16816(Cs[mt][nt], fal, fbh[nt]);
                }
            }
        }

        #pragma unroll
        for (int mt = 0; mt < 4; mt++) {
            #pragma unroll
            for (int nt = 0; nt < 4; nt++) {
                int col = wn * 32 + nt * 8 + 2 * cq;
                float m0 = s_msk[col], m1 = s_msk[col + 1];
                #pragma unroll
                for (int hf = 0; hf < 2; hf++) {
                    int row = wq * 64 + mt * 16 + r + hf * 8;
                    float iv = inv_r[mt][hf];
                    float e0 = __expf(Cs[mt][nt][hf*2+0]) * m0 * iv;
                    float e1 = __expf(Cs[mt][nt][hf*2+1]) * m1 * iv;
                    if (attn)
                        *(float2*)(attn + ((size_t)bh * LL + q0 + row) * LL + k0g + col) =
                            make_float2(e0, e1);
                    __nv_bfloat16 h0,l0,h1,l1; split_bf(e0,h0,l0); split_bf(e1,h1,l1);
                    *(__nv_bfloat162*)(Ph + (size_t)row * SV + col) = __halves2bfloat162(h0,h1);
                    *(__nv_bfloat162*)(Pl + (size_t)row * SV + col) = __halves2bfloat162(l0,l1);
                }
            }
        }
        __syncthreads();

        #pragma unroll
        for (int ks = 0; ks < 8; ks++) {
            uint32_t vbh[2][2], vbl[2][2];
            #pragma unroll
            for (int nt = 0; nt < 2; nt++) {
                ldB(vbh[nt], Vh, SV, wn * 16 + nt * 8, ks * 16, lane);
                ldB(vbl[nt], Vl, SV, wn * 16 + nt * 8, ks * 16, lane);
            }
            #pragma unroll
            for (int mt = 0; mt < 4; mt++) {
                uint32_t pah[4], pal[4];
                ldA(pah, Ph, SV, wq * 64 + mt * 16, ks * 16, lane);
                ldA(pal, Pl, SV, wq * 64 + mt * 16, ks * 16, lane);
                #pragma unroll
                for (int nt = 0; nt < 2; nt++) {
                    mma16816(O[mt][nt], pah, vbh[nt]);
                    mma16816(O[mt][nt], pah, vbl[nt]);
                    mma16816(O[mt][nt], pal, vbh[nt]);
                }
            }
        }
    }

    // ---- O epilogue (already normalized) ----
    #pragma unroll
    for (int mt = 0; mt < 4; mt++) {
        #pragma unroll
        for (int nt = 0; nt < 2; nt++) {
            int d = wn * 16 + nt * 8 + 2 * cq;
            #pragma unroll
            for (int hf = 0; hf < 2; hf++) {
                int row = wq * 64 + mt * 16 + r + hf * 8;
                float v0 = O[mt][nt][hf*2+0];
                float v1 = O[mt][nt][hf*2+1];
                __nv_bfloat16 h0,l0,h1,l1; split_bf(v0,h0,l0); split_bf(v1,h1,l1);
                size_t idx = ((size_t)b * LL + q0 + row) * DM + (bh & 15) * 64 + d;
                *(__nv_bfloat162*)(g_Oh + idx) = __halves2bfloat162(h0, h1);
                *(__nv_bfloat162*)(g_Ol + idx) = __halves2bfloat162(l0, l1);
            }
        }
    }
}

// ============================================================================
extern "C" void kernel_launch(void* const* d_in, const int* in_sizes, int n_in,
                              void* d_out, int out_size)
{
    const float* x    = (const float*)d_in[0];
    const int*   mask = (const int*)  d_in[1];
    const float* bq   = (const float*)d_in[3];
    const float* bk   = (const float*)d_in[5];
    const float* bv   = (const float*)d_in[7];
    const float* bo   = (const float*)d_in[9];
    float* out = (float*)d_out;

    const size_t out_elems  = (size_t)MM * DM;
    const size_t attn_elems = (size_t)BB * NH * LL * LL;
    float* attn = ((size_t)out_size >= out_elems + attn_elems) ? (out + out_elems) : nullptr;

    const int smem_proj = 40960;
    const int smem_attn = 178176;
    cudaFuncSetAttribute(proj_kernel, cudaFuncAttributeMaxDynamicSharedMemorySize, smem_proj);
    cudaFuncSetAttribute(attn_kernel, cudaFuncAttributeMaxDynamicSharedMemorySize, smem_attn);

    const size_t total_cvt = (size_t)MM * DM + 4 * (size_t)DM * DM;  // 8M
    cvt_all_kernel<<<(int)(total_cvt / 256), 256>>>(
        x, (const float*)d_in[2], (const float*)d_in[4],
        (const float*)d_in[6], (const float*)d_in[8]);

    proj_kernel<<<dim3(8, 32, 3), 256, smem_proj>>>(bq, bk, bv, nullptr, -1);

    attn_kernel<<<dim3(LL / 128, BB * NH), 256, smem_attn>>>(mask, attn);

    proj_kernel<<<dim3(8, 32, 1), 256, smem_proj>>>(bo, nullptr, nullptr, out, 3);
}

// round 6
// speedup vs baseline: 2.3903x; 1.1001x over previous
#include <cuda_runtime.h>
#include <cuda_bf16.h>
#include <cstdint>

#define BB 2
#define LL 2048
#define DM 1024
#define NH 16
#define MM (BB*LL)

// ---------------- device scratch (bf16 hi/lo pairs) -------------------------
__device__ __align__(16) __nv_bfloat16 g_xh[MM*DM], g_xl[MM*DM];
__device__ __align__(16) __nv_bfloat16 g_wh[4][DM*DM], g_wl[4][DM*DM];  // Wq,Wk,Wv,Wo
__device__ __align__(16) __nv_bfloat16 g_Qh[MM*DM], g_Ql[MM*DM];        // [bh][l][64], pre-scaled 1/8
__device__ __align__(16) __nv_bfloat16 g_Kh[MM*DM], g_Kl[MM*DM];        // [bh][l][64]
__device__ __align__(16) __nv_bfloat16 g_Vh[MM*DM], g_Vl[MM*DM];        // transposed [bh][d][l]
__device__ __align__(16) __nv_bfloat16 g_Oh[MM*DM], g_Ol[MM*DM];        // [b][l][1024]

// ---------------- mma / ldmatrix / cp.async helpers -------------------------
__device__ __forceinline__ void mma16816(float* c, const uint32_t* a, const uint32_t* b){
    asm volatile("mma.sync.aligned.m16n8k16.row.col.f32.bf16.bf16.f32 "
        "{%0,%1,%2,%3}, {%4,%5,%6,%7}, {%8,%9}, {%0,%1,%2,%3};"
        : "+f"(c[0]), "+f"(c[1]), "+f"(c[2]), "+f"(c[3])
        : "r"(a[0]), "r"(a[1]), "r"(a[2]), "r"(a[3]), "r"(b[0]), "r"(b[1]));
}
__device__ __forceinline__ uint32_t smem_u32(const void* p){
    uint32_t a;
    asm("{ .reg .u64 t; cvta.to.shared.u64 t, %1; cvt.u32.u64 %0, t; }" : "=r"(a) : "l"(p));
    return a;
}
// A fragment m16k16 via ldmatrix x4 from row-major smem (stride S elems)
__device__ __forceinline__ void ldmA(uint32_t* a, const __nv_bfloat16* s, int S, int m0, int k0, int lane){
    const __nv_bfloat16* p = s + (size_t)(m0 + (lane & 15)) * S + k0 + ((lane >> 4) << 3);
    uint32_t addr = smem_u32(p);
    asm volatile("ldmatrix.sync.aligned.m8n8.x4.shared.b16 {%0,%1,%2,%3}, [%4];"
        : "=r"(a[0]), "=r"(a[1]), "=r"(a[2]), "=r"(a[3]) : "r"(addr));
}
// B fragment n8k16 via ldmatrix x2 from row-major [n][k] smem (stride S elems)
__device__ __forceinline__ void ldmB(uint32_t* b, const __nv_bfloat16* s, int S, int n0, int k0, int lane){
    const __nv_bfloat16* p = s + (size_t)(n0 + (lane & 7)) * S + k0 + (((lane >> 3) & 1) << 3);
    uint32_t addr = smem_u32(p);
    asm volatile("ldmatrix.sync.aligned.m8n8.x2.shared.b16 {%0,%1}, [%2];"
        : "=r"(b[0]), "=r"(b[1]) : "r"(addr));
}
__device__ __forceinline__ void cp16(const __nv_bfloat16* dst, const __nv_bfloat16* src){
    asm volatile("cp.async.ca.shared.global [%0], [%1], 16;" :: "r"(smem_u32(dst)), "l"(src));
}
#define CP_COMMIT() asm volatile("cp.async.commit_group;" ::: "memory")
__device__ __forceinline__ void split_bf(float v, __nv_bfloat16& h, __nv_bfloat16& l){
    h = __float2bfloat16(v);
    l = __float2bfloat16(v - __bfloat162float(h));
}

// ============================================================================
// fp32 -> hi/lo bf16 conversion, all tensors in one launch
// ============================================================================
__global__ __launch_bounds__(256) void cvt_all_kernel(
    const float* __restrict__ x,  const float* __restrict__ wq,
    const float* __restrict__ wk, const float* __restrict__ wv,
    const float* __restrict__ wo)
{
    size_t i = (size_t)blockIdx.x * 256 + threadIdx.x;
    const float* s; __nv_bfloat16 *dh, *dl; size_t off;
    if (i < (size_t)MM * DM) {
        s = x; dh = g_xh; dl = g_xl; off = i;
    } else {
        size_t j = i - (size_t)MM * DM;
        int t = (int)(j >> 20);
        off = j & ((1u << 20) - 1);
        s = (t == 0) ? wq : (t == 1) ? wk : (t == 2) ? wv : wo;
        dh = g_wh[t]; dl = g_wl[t];
    }
    float v = s[off];
    __nv_bfloat16 h, l; split_bf(v, h, l);
    dh[off] = h; dl[off] = l;
}

// ============================================================================
// projection GEMM, cp.async double-buffered, ldmatrix fragments.
// mode_arg -1: mode = blockIdx.z in {0:Q,1:K,2:V}; mode_arg 3: out proj.
// ============================================================================
#define SA 40
#define STG (4*128*SA)   // elems per stage = 20480
__global__ __launch_bounds__(256, 1) void proj_kernel(
    const float* __restrict__ b0, const float* __restrict__ b1,
    const float* __restrict__ b2, float* __restrict__ fout, int mode_arg)
{
    extern __shared__ char smraw[];
    __nv_bfloat16* S = (__nv_bfloat16*)smraw;      // 2 stages x 4 tiles x 128 x SA
    __shared__ float s_bias[128];

    const int mode = (mode_arg < 0) ? (int)blockIdx.z : mode_arg;
    const float* bias = (mode == 1) ? b1 : (mode == 2) ? b2 : b0;
    const __nv_bfloat16* gAh = (mode < 3) ? g_xh : g_Oh;
    const __nv_bfloat16* gAl = (mode < 3) ? g_xl : g_Ol;
    const __nv_bfloat16* gBh = g_wh[mode];
    const __nv_bfloat16* gBl = g_wl[mode];

    const int bm = blockIdx.y * 128, bn = blockIdx.x * 128;
    const int tid = threadIdx.x, w = tid >> 5, lane = tid & 31;
    const int wm = w >> 2, wn = w & 3;
    if (tid < 128) s_bias[tid] = bias[bn + tid];

    float C[4][4][4];
    #pragma unroll
    for (int i = 0; i < 4; i++)
        #pragma unroll
        for (int j = 0; j < 4; j++)
            #pragma unroll
            for (int q = 0; q < 4; q++) C[i][j][q] = 0.f;

    // prefetch stage 0
    #pragma unroll
    for (int i = tid; i < 2048; i += 256) {
        int t = i >> 9, e = i & 511, r = e >> 2, c4 = e & 3;
        const __nv_bfloat16* src = (t==0)?gAh:(t==1)?gAl:(t==2)?gBh:gBl;
        int rowbase = (t < 2) ? bm : bn;
        cp16(S + t * 5120 + r * SA + c4 * 8,
             src + (size_t)(rowbase + r) * DM + c4 * 8);
    }
    CP_COMMIT();

    for (int it = 0; it < 32; it++) {
        const int cur = it & 1;
        if (it + 1 < 32) {
            const int k0n = (it + 1) * 32, nxt = cur ^ 1;
            #pragma unroll
            for (int i = tid; i < 2048; i += 256) {
                int t = i >> 9, e = i & 511, r = e >> 2, c4 = e & 3;
                const __nv_bfloat16* src = (t==0)?gAh:(t==1)?gAl:(t==2)?gBh:gBl;
                int rowbase = (t < 2) ? bm : bn;
                cp16(S + nxt * STG + t * 5120 + r * SA + c4 * 8,
                     src + (size_t)(rowbase + r) * DM + k0n + c4 * 8);
            }
            CP_COMMIT();
            asm volatile("cp.async.wait_group 1;" ::: "memory");
        } else {
            asm volatile("cp.async.wait_group 0;" ::: "memory");
        }
        __syncthreads();

        const __nv_bfloat16 *Ah = S + cur * STG,        *Al = Ah + 5120,
                            *Bh = Ah + 10240,            *Bl = Ah + 15360;
        #pragma unroll
        for (int ks = 0; ks < 2; ks++) {
            uint32_t fbh[4][2], fbl[4][2];
            #pragma unroll
            for (int nt = 0; nt < 4; nt++) {
                ldmB(fbh[nt], Bh, SA, wn * 32 + nt * 8, ks * 16, lane);
                ldmB(fbl[nt], Bl, SA, wn * 32 + nt * 8, ks * 16, lane);
            }
            #pragma unroll
            for (int mt = 0; mt < 4; mt++) {
                uint32_t fah[4], fal[4];
                ldmA(fah, Ah, SA, wm * 64 + mt * 16, ks * 16, lane);
                ldmA(fal, Al, SA, wm * 64 + mt * 16, ks * 16, lane);
                #pragma unroll
                for (int nt = 0; nt < 4; nt++) {
                    mma16816(C[mt][nt], fah, fbh[nt]);
                    mma16816(C[mt][nt], fah, fbl[nt]);
                    mma16816(C[mt][nt], fal, fbh[nt]);
                }
            }
        }
        __syncthreads();
    }

    const int r = lane >> 2, cq = lane & 3;
    const float scl = (mode == 0) ? 0.125f : 1.0f;
    #pragma unroll
    for (int mt = 0; mt < 4; mt++) {
        #pragma unroll
        for (int nt = 0; nt < 4; nt++) {
            int nloc = wn * 32 + nt * 8 + 2 * cq;
            int n = bn + nloc;
            #pragma unroll
            for (int hf = 0; hf < 2; hf++) {
                int m = bm + wm * 64 + mt * 16 + r + hf * 8;
                float v0 = (C[mt][nt][hf*2+0] + s_bias[nloc])     * scl;
                float v1 = (C[mt][nt][hf*2+1] + s_bias[nloc + 1]) * scl;
                if (mode == 3) {
                    *(float2*)(fout + (size_t)m * DM + n) = make_float2(v0, v1);
                } else {
                    int bidx = m >> 11, l = m & 2047, h = n >> 6, d = n & 63;
                    __nv_bfloat16 h0,l0,h1,l1; split_bf(v0,h0,l0); split_bf(v1,h1,l1);
                    if (mode < 2) {
                        __nv_bfloat16* DH = mode == 0 ? g_Qh : g_Kh;
                        __nv_bfloat16* DL = mode == 0 ? g_Ql : g_Kl;
                        size_t idx = (((size_t)bidx * NH + h) * LL + l) * 64 + d;
                        *(__nv_bfloat162*)(DH + idx) = __halves2bfloat162(h0, h1);
                        *(__nv_bfloat162*)(DL + idx) = __halves2bfloat162(l0, l1);
                    } else {
                        size_t idx = (((size_t)bidx * NH + h) * 64 + d) * LL + l;
                        g_Vh[idx] = h0; g_Vl[idx] = l0;
                        g_Vh[idx + LL] = h1; g_Vl[idx + LL] = l1;
                    }
                }
            }
        }
    }
}

// ============================================================================
// fused attention, TWO PASS, ldmatrix fragments.
// ============================================================================
#define SQ 72
#define SV 136
__global__ __launch_bounds__(256, 1) void attn_kernel(const int* __restrict__ mask,
                                                      float* __restrict__ attn){
    extern __shared__ char smraw[];
    __nv_bfloat16* S = (__nv_bfloat16*)smraw;
    __nv_bfloat16 *Qh = S,           *Ql = S + 9216,
                  *Kh = S + 18432,   *Kl = S + 27648,
                  *Vh = S + 36864,   *Vl = S + 45568,
                  *Ph = S + 54272,   *Pl = S + 71680;
    __shared__ float s_msk[128];
    __shared__ float s_rs[128][4];
    __shared__ float s_inv[128];

    const int bh = blockIdx.y, q0 = blockIdx.x * 128, b = bh >> 4;
    const int tid = threadIdx.x, w = tid >> 5, lane = tid & 31;
    const int wq = w >> 2, wn = w & 3;
    const int r = lane >> 2, cq = lane & 3;

    #pragma unroll
    for (int i = tid; i < 2048; i += 256) {
        int t = i >> 10, e = i & 1023, rr = e >> 3, c8 = e & 7;
        const __nv_bfloat16* src = (t ? g_Ql : g_Qh) + ((size_t)bh * LL + q0) * 64;
        __nv_bfloat16* dst = t ? Ql : Qh;
        cp16(dst + rr * SQ + c8 * 8, src + (size_t)rr * 64 + c8 * 8);
    }
    CP_COMMIT();

    float rs[4][2] = {{0,0},{0,0},{0,0},{0,0}};

    // ---------------- pass 1: rowsums (2-MMA S) ----------------
    for (int kt = 0; kt < 16; kt++) {
        const int k0g = kt * 128;
        __syncthreads();
        #pragma unroll
        for (int i = tid; i < 1024; i += 256) {
            int rr = i >> 3, c8 = i & 7;
            const __nv_bfloat16* src = g_Kh + ((size_t)bh * LL + k0g) * 64;
            cp16(Kh + rr * SQ + c8 * 8, src + (size_t)rr * 64 + c8 * 8);
        }
        CP_COMMIT();
        if (tid < 128) s_msk[tid] = mask[b * LL + k0g + tid] ? 1.f : 0.f;
        asm volatile("cp.async.wait_group 0;" ::: "memory");
        __syncthreads();

        float Cs[4][4][4];
        #pragma unroll
        for (int i=0;i<4;i++) for (int j=0;j<4;j++) for (int q=0;q<4;q++) Cs[i][j][q]=0.f;
        #pragma unroll
        for (int ks = 0; ks < 4; ks++) {
            uint32_t fbh[4][2];
            #pragma unroll
            for (int nt = 0; nt < 4; nt++)
                ldmB(fbh[nt], Kh, SQ, wn * 32 + nt * 8, ks * 16, lane);
            #pragma unroll
            for (int mt = 0; mt < 4; mt++) {
                uint32_t fah[4], fal[4];
                ldmA(fah, Qh, SQ, wq * 64 + mt * 16, ks * 16, lane);
                ldmA(fal, Ql, SQ, wq * 64 + mt * 16, ks * 16, lane);
                #pragma unroll
                for (int nt = 0; nt < 4; nt++) {
                    mma16816(Cs[mt][nt], fah, fbh[nt]);
                    mma16816(Cs[mt][nt], fal, fbh[nt]);
                }
            }
        }
        #pragma unroll
        for (int mt = 0; mt < 4; mt++)
            #pragma unroll
            for (int nt = 0; nt < 4; nt++) {
                int col = wn * 32 + nt * 8 + 2 * cq;
                float m0 = s_msk[col], m1 = s_msk[col + 1];
                #pragma unroll
                for (int hf = 0; hf < 2; hf++)
                    rs[mt][hf] += __expf(Cs[mt][nt][hf*2+0]) * m0
                                + __expf(Cs[mt][nt][hf*2+1]) * m1;
            }
    }

    #pragma unroll
    for (int mt = 0; mt < 4; mt++)
        #pragma unroll
        for (int hf = 0; hf < 2; hf++) {
            rs[mt][hf] += __shfl_xor_sync(0xffffffffu, rs[mt][hf], 1);
            rs[mt][hf] += __shfl_xor_sync(0xffffffffu, rs[mt][hf], 2);
        }
    __syncthreads();
    if (cq == 0) {
        #pragma unroll
        for (int mt = 0; mt < 4; mt++)
            #pragma unroll
            for (int hf = 0; hf < 2; hf++)
                s_rs[wq * 64 + mt * 16 + r + hf * 8][wn] = rs[mt][hf];
    }
    __syncthreads();
    if (tid < 128)
        s_inv[tid] = 1.f / (s_rs[tid][0] + s_rs[tid][1] + s_rs[tid][2] + s_rs[tid][3]);
    __syncthreads();

    float O[4][2][4];
    #pragma unroll
    for (int i=0;i<4;i++) for (int j=0;j<2;j++) for (int q=0;q<4;q++) O[i][j][q]=0.f;
    float inv_r[4][2];
    #pragma unroll
    for (int mt = 0; mt < 4; mt++)
        #pragma unroll
        for (int hf = 0; hf < 2; hf++)
            inv_r[mt][hf] = s_inv[wq * 64 + mt * 16 + r + hf * 8];

    // ---------------- pass 2: normalized attn + O ----------------
    for (int kt = 0; kt < 16; kt++) {
        const int k0g = kt * 128;
        __syncthreads();
        #pragma unroll
        for (int i = tid; i < 2048; i += 256) {
            int t = i >> 10, e = i & 1023, rr = e >> 3, c8 = e & 7;
            const __nv_bfloat16* src = (t ? g_Kl : g_Kh) + ((size_t)bh * LL + k0g) * 64;
            __nv_bfloat16* dst = t ? Kl : Kh;
            cp16(dst + rr * SQ + c8 * 8, src + (size_t)rr * 64 + c8 * 8);
        }
        #pragma unroll
        for (int i = tid; i < 2048; i += 256) {
            int t = i >> 10, e = i & 1023, rr = e >> 4, c8 = e & 15;
            const __nv_bfloat16* src = (t ? g_Vl : g_Vh) + (size_t)bh * 64 * LL;
            __nv_bfloat16* dst = t ? Vl : Vh;
            cp16(dst + rr * SV + c8 * 8, src + (size_t)rr * LL + k0g + c8 * 8);
        }
        CP_COMMIT();
        if (tid < 128) s_msk[tid] = mask[b * LL + k0g + tid] ? 1.f : 0.f;
        asm volatile("cp.async.wait_group 0;" ::: "memory");
        __syncthreads();

        float Cs[4][4][4];
        #pragma unroll
        for (int i=0;i<4;i++) for (int j=0;j<4;j++) for (int q=0;q<4;q++) Cs[i][j][q]=0.f;
        #pragma unroll
        for (int ks = 0; ks < 4; ks++) {
            uint32_t fbh[4][2], fbl[4][2];
            #pragma unroll
            for (int nt = 0; nt < 4; nt++) {
                ldmB(fbh[nt], Kh, SQ, wn * 32 + nt * 8, ks * 16, lane);
                ldmB(fbl[nt], Kl, SQ, wn * 32 + nt * 8, ks * 16, lane);
            }
            #pragma unroll
            for (int mt = 0; mt < 4; mt++) {
                uint32_t fah[4], fal[4];
                ldmA(fah, Qh, SQ, wq * 64 + mt * 16, ks * 16, lane);
                ldmA(fal, Ql, SQ, wq * 64 + mt * 16, ks * 16, lane);
                #pragma unroll
                for (int nt = 0; nt < 4; nt++) {
                    mma16816(Cs[mt][nt], fah, fbh[nt]);
                    mma16816(Cs[mt][nt], fah, fbl[nt]);
                    mma16816(Cs[mt][nt], fal, fbh[nt]);
                }
            }
        }

        #pragma unroll
        for (int mt = 0; mt < 4; mt++) {
            #pragma unroll
            for (int nt = 0; nt < 4; nt++) {
                int col = wn * 32 + nt * 8 + 2 * cq;
                float m0 = s_msk[col], m1 = s_msk[col + 1];
                #pragma unroll
                for (int hf = 0; hf < 2; hf++) {
                    int row = wq * 64 + mt * 16 + r + hf * 8;
                    float iv = inv_r[mt][hf];
                    float e0 = __expf(Cs[mt][nt][hf*2+0]) * m0 * iv;
                    float e1 = __expf(Cs[mt][nt][hf*2+1]) * m1 * iv;
                    if (attn)
                        *(float2*)(attn + ((size_t)bh * LL + q0 + row) * LL + k0g + col) =
                            make_float2(e0, e1);
                    __nv_bfloat16 h0,l0,h1,l1; split_bf(e0,h0,l0); split_bf(e1,h1,l1);
                    *(__nv_bfloat162*)(Ph + (size_t)row * SV + col) = __halves2bfloat162(h0,h1);
                    *(__nv_bfloat162*)(Pl + (size_t)row * SV + col) = __halves2bfloat162(l0,l1);
                }
            }
        }
        __syncthreads();

        #pragma unroll
        for (int ks = 0; ks < 8; ks++) {
            uint32_t vbh[2][2], vbl[2][2];
            #pragma unroll
            for (int nt = 0; nt < 2; nt++) {
                ldmB(vbh[nt], Vh, SV, wn * 16 + nt * 8, ks * 16, lane);
                ldmB(vbl[nt], Vl, SV, wn * 16 + nt * 8, ks * 16, lane);
            }
            #pragma unroll
            for (int mt = 0; mt < 4; mt++) {
                uint32_t pah[4], pal[4];
                ldmA(pah, Ph, SV, wq * 64 + mt * 16, ks * 16, lane);
                ldmA(pal, Pl, SV, wq * 64 + mt * 16, ks * 16, lane);
                #pragma unroll
                for (int nt = 0; nt < 2; nt++) {
                    mma16816(O[mt][nt], pah, vbh[nt]);
                    mma16816(O[mt][nt], pah, vbl[nt]);
                    mma16816(O[mt][nt], pal, vbh[nt]);
                }
            }
        }
    }

    // ---- O epilogue (already normalized) ----
    #pragma unroll
    for (int mt = 0; mt < 4; mt++) {
        #pragma unroll
        for (int nt = 0; nt < 2; nt++) {
            int d = wn * 16 + nt * 8 + 2 * cq;
            #pragma unroll
            for (int hf = 0; hf < 2; hf++) {
                int row = wq * 64 + mt * 16 + r + hf * 8;
                __nv_bfloat16 h0,l0,h1,l1;
                split_bf(O[mt][nt][hf*2+0], h0, l0);
                split_bf(O[mt][nt][hf*2+1], h1, l1);
                size_t idx = ((size_t)b * LL + q0 + row) * DM + (bh & 15) * 64 + d;
                *(__nv_bfloat162*)(g_Oh + idx) = __halves2bfloat162(h0, h1);
                *(__nv_bfloat162*)(g_Ol + idx) = __halves2bfloat162(l0, l1);
            }
        }
    }
}

// ============================================================================
extern "C" void kernel_launch(void* const* d_in, const int* in_sizes, int n_in,
                              void* d_out, int out_size)
{
    const float* x    = (const float*)d_in[0];
    const int*   mask = (const int*)  d_in[1];
    const float* bq   = (const float*)d_in[3];
    const float* bk   = (const float*)d_in[5];
    const float* bv   = (const float*)d_in[7];
    const float* bo   = (const float*)d_in[9];
    float* out = (float*)d_out;

    const size_t out_elems  = (size_t)MM * DM;
    const size_t attn_elems = (size_t)BB * NH * LL * LL;
    float* attn = ((size_t)out_size >= out_elems + attn_elems) ? (out + out_elems) : nullptr;

    const int smem_proj = 2 * STG * 2;          // 81920 B
    const int smem_attn = 178176;
    cudaFuncSetAttribute(proj_kernel, cudaFuncAttributeMaxDynamicSharedMemorySize, smem_proj);
    cudaFuncSetAttribute(attn_kernel, cudaFuncAttributeMaxDynamicSharedMemorySize, smem_attn);

    const size_t total_cvt = (size_t)MM * DM + 4 * (size_t)DM * DM;
    cvt_all_kernel<<<(int)(total_cvt / 256), 256>>>(
        x, (const float*)d_in[2], (const float*)d_in[4],
        (const float*)d_in[6], (const float*)d_in[8]);

    proj_kernel<<<dim3(8, 32, 3), 256, smem_proj>>>(bq, bk, bv, nullptr, -1);

    attn_kernel<<<dim3(LL / 128, BB * NH), 256, smem_attn>>>(mask, attn);

    proj_kernel<<<dim3(8, 32, 1), 256, smem_proj>>>(bo, nullptr, nullptr, out, 3);
}

// round 7
// speedup vs baseline: 2.6536x; 1.1102x over previous
#include <cuda_runtime.h>
#include <cuda_bf16.h>
#include <cstdint>

#define BB 2
#define LL 2048
#define DM 1024
#define NH 16
#define MM (BB*LL)

// ---------------- device scratch (bf16 hi/lo pairs) -------------------------
__device__ __align__(16) __nv_bfloat16 g_xh[MM*DM], g_xl[MM*DM];
__device__ __align__(16) __nv_bfloat16 g_wh[4][DM*DM], g_wl[4][DM*DM];
__device__ __align__(16) __nv_bfloat16 g_Qh[MM*DM], g_Ql[MM*DM];   // [bh][l][64], pre-scaled 1/8
__device__ __align__(16) __nv_bfloat16 g_Kh[MM*DM], g_Kl[MM*DM];   // [bh][l][64]
__device__ __align__(16) __nv_bfloat16 g_Vh[MM*DM], g_Vl[MM*DM];   // transposed [bh][d][l]
__device__ __align__(16) __nv_bfloat16 g_Oh[MM*DM], g_Ol[MM*DM];   // [b][l][1024]

// ---------------- mma / ldmatrix / cp.async helpers -------------------------
__device__ __forceinline__ void mma16816(float* c, const uint32_t* a, const uint32_t* b){
    asm volatile("mma.sync.aligned.m16n8k16.row.col.f32.bf16.bf16.f32 "
        "{%0,%1,%2,%3}, {%4,%5,%6,%7}, {%8,%9}, {%0,%1,%2,%3};"
        : "+f"(c[0]), "+f"(c[1]), "+f"(c[2]), "+f"(c[3])
        : "r"(a[0]), "r"(a[1]), "r"(a[2]), "r"(a[3]), "r"(b[0]), "r"(b[1]));
}
__device__ __forceinline__ uint32_t smem_u32(const void* p){
    uint32_t a;
    asm("{ .reg .u64 t; cvta.to.shared.u64 t, %1; cvt.u32.u64 %0, t; }" : "=r"(a) : "l"(p));
    return a;
}
__device__ __forceinline__ void ldmA(uint32_t* a, const __nv_bfloat16* s, int S, int m0, int k0, int lane){
    const __nv_bfloat16* p = s + (size_t)(m0 + (lane & 15)) * S + k0 + ((lane >> 4) << 3);
    asm volatile("ldmatrix.sync.aligned.m8n8.x4.shared.b16 {%0,%1,%2,%3}, [%4];"
        : "=r"(a[0]), "=r"(a[1]), "=r"(a[2]), "=r"(a[3]) : "r"(smem_u32(p)));
}
__device__ __forceinline__ void ldmB(uint32_t* b, const __nv_bfloat16* s, int S, int n0, int k0, int lane){
    const __nv_bfloat16* p = s + (size_t)(n0 + (lane & 7)) * S + k0 + (((lane >> 3) & 1) << 3);
    asm volatile("ldmatrix.sync.aligned.m8n8.x2.shared.b16 {%0,%1}, [%2];"
        : "=r"(b[0]), "=r"(b[1]) : "r"(smem_u32(p)));
}
__device__ __forceinline__ void cp16(const __nv_bfloat16* dst, const __nv_bfloat16* src){
    asm volatile("cp.async.ca.shared.global [%0], [%1], 16;" :: "r"(smem_u32(dst)), "l"(src));
}
#define CP_COMMIT() asm volatile("cp.async.commit_group;" ::: "memory")
__device__ __forceinline__ void split_bf(float v, __nv_bfloat16& h, __nv_bfloat16& l){
    h = __float2bfloat16(v);
    l = __float2bfloat16(v - __bfloat162float(h));
}

// ============================================================================
// fp32 -> hi/lo bf16, vectorized, all tensors in one launch (8M elems / 4)
// ============================================================================
__global__ __launch_bounds__(256) void cvt_all_kernel(
    const float* __restrict__ x,  const float* __restrict__ wq,
    const float* __restrict__ wk, const float* __restrict__ wv,
    const float* __restrict__ wo)
{
    size_t i4 = ((size_t)blockIdx.x * 256 + threadIdx.x) * 4;
    const float* s; __nv_bfloat16 *dh, *dl; size_t off;
    if (i4 < (size_t)MM * DM) {
        s = x; dh = g_xh; dl = g_xl; off = i4;
    } else {
        size_t j = i4 - (size_t)MM * DM;
        int t = (int)(j >> 20);
        off = j & ((1u << 20) - 1);
        s = (t == 0) ? wq : (t == 1) ? wk : (t == 2) ? wv : wo;
        dh = g_wh[t]; dl = g_wl[t];
    }
    float4 v = *(const float4*)(s + off);
    __nv_bfloat16 h0,l0,h1,l1,h2,l2,h3,l3;
    split_bf(v.x,h0,l0); split_bf(v.y,h1,l1); split_bf(v.z,h2,l2); split_bf(v.w,h3,l3);
    __nv_bfloat162 hh[2] = {__halves2bfloat162(h0,h1), __halves2bfloat162(h2,h3)};
    __nv_bfloat162 ll[2] = {__halves2bfloat162(l0,l1), __halves2bfloat162(l2,l3)};
    *(uint2*)(dh + off) = *(uint2*)hh;
    *(uint2*)(dl + off) = *(uint2*)ll;
}

// ============================================================================
// projection GEMM, cp.async double-buffered, ldmatrix, 2 CTAs/SM.
// ============================================================================
#define SA 40
#define STG (4*128*SA)
__global__ __launch_bounds__(256, 2) void proj_kernel(
    const float* __restrict__ b0, const float* __restrict__ b1,
    const float* __restrict__ b2, float* __restrict__ fout, int mode_arg)
{
    extern __shared__ char smraw[];
    __nv_bfloat16* S = (__nv_bfloat16*)smraw;
    __shared__ float s_bias[128];

    const int mode = (mode_arg < 0) ? (int)blockIdx.z : mode_arg;
    const float* bias = (mode == 1) ? b1 : (mode == 2) ? b2 : b0;
    const __nv_bfloat16* gAh = (mode < 3) ? g_xh : g_Oh;
    const __nv_bfloat16* gAl = (mode < 3) ? g_xl : g_Ol;
    const __nv_bfloat16* gBh = g_wh[mode];
    const __nv_bfloat16* gBl = g_wl[mode];

    const int bm = blockIdx.y * 128, bn = blockIdx.x * 128;
    const int tid = threadIdx.x, w = tid >> 5, lane = tid & 31;
    const int wm = w >> 2, wn = w & 3;
    if (tid < 128) s_bias[tid] = bias[bn + tid];

    float C[4][4][4];
    #pragma unroll
    for (int i = 0; i < 4; i++)
        #pragma unroll
        for (int j = 0; j < 4; j++)
            #pragma unroll
            for (int q = 0; q < 4; q++) C[i][j][q] = 0.f;

    #pragma unroll
    for (int i = tid; i < 2048; i += 256) {
        int t = i >> 9, e = i & 511, r = e >> 2, c4 = e & 3;
        const __nv_bfloat16* src = (t==0)?gAh:(t==1)?gAl:(t==2)?gBh:gBl;
        int rowbase = (t < 2) ? bm : bn;
        cp16(S + t * 5120 + r * SA + c4 * 8, src + (size_t)(rowbase + r) * DM + c4 * 8);
    }
    CP_COMMIT();

    for (int it = 0; it < 32; it++) {
        const int cur = it & 1;
        if (it + 1 < 32) {
            const int k0n = (it + 1) * 32, nxt = cur ^ 1;
            #pragma unroll
            for (int i = tid; i < 2048; i += 256) {
                int t = i >> 9, e = i & 511, r = e >> 2, c4 = e & 3;
                const __nv_bfloat16* src = (t==0)?gAh:(t==1)?gAl:(t==2)?gBh:gBl;
                int rowbase = (t < 2) ? bm : bn;
                cp16(S + nxt * STG + t * 5120 + r * SA + c4 * 8,
                     src + (size_t)(rowbase + r) * DM + k0n + c4 * 8);
            }
            CP_COMMIT();
            asm volatile("cp.async.wait_group 1;" ::: "memory");
        } else {
            asm volatile("cp.async.wait_group 0;" ::: "memory");
        }
        __syncthreads();

        const __nv_bfloat16 *Ah = S + cur * STG, *Al = Ah + 5120,
                            *Bh = Ah + 10240,     *Bl = Ah + 15360;
        #pragma unroll
        for (int ks = 0; ks < 2; ks++) {
            uint32_t fbh[4][2], fbl[4][2];
            #pragma unroll
            for (int nt = 0; nt < 4; nt++) {
                ldmB(fbh[nt], Bh, SA, wn * 32 + nt * 8, ks * 16, lane);
                ldmB(fbl[nt], Bl, SA, wn * 32 + nt * 8, ks * 16, lane);
            }
            #pragma unroll
            for (int mt = 0; mt < 4; mt++) {
                uint32_t fah[4], fal[4];
                ldmA(fah, Ah, SA, wm * 64 + mt * 16, ks * 16, lane);
                ldmA(fal, Al, SA, wm * 64 + mt * 16, ks * 16, lane);
                #pragma unroll
                for (int nt = 0; nt < 4; nt++) {
                    mma16816(C[mt][nt], fah, fbh[nt]);
                    mma16816(C[mt][nt], fah, fbl[nt]);
                    mma16816(C[mt][nt], fal, fbh[nt]);
                }
            }
        }
        __syncthreads();
    }

    const int r = lane >> 2, cq = lane & 3;
    const float scl = (mode == 0) ? 0.125f : 1.0f;
    #pragma unroll
    for (int mt = 0; mt < 4; mt++) {
        #pragma unroll
        for (int nt = 0; nt < 4; nt++) {
            int nloc = wn * 32 + nt * 8 + 2 * cq;
            int n = bn + nloc;
            #pragma unroll
            for (int hf = 0; hf < 2; hf++) {
                int m = bm + wm * 64 + mt * 16 + r + hf * 8;
                float v0 = (C[mt][nt][hf*2+0] + s_bias[nloc])     * scl;
                float v1 = (C[mt][nt][hf*2+1] + s_bias[nloc + 1]) * scl;
                if (mode == 3) {
                    *(float2*)(fout + (size_t)m * DM + n) = make_float2(v0, v1);
                } else {
                    int bidx = m >> 11, l = m & 2047, h = n >> 6, d = n & 63;
                    __nv_bfloat16 h0,l0,h1,l1; split_bf(v0,h0,l0); split_bf(v1,h1,l1);
                    if (mode < 2) {
                        __nv_bfloat16* DH = mode == 0 ? g_Qh : g_Kh;
                        __nv_bfloat16* DL = mode == 0 ? g_Ql : g_Kl;
                        size_t idx = (((size_t)bidx * NH + h) * LL + l) * 64 + d;
                        *(__nv_bfloat162*)(DH + idx) = __halves2bfloat162(h0, h1);
                        *(__nv_bfloat162*)(DL + idx) = __halves2bfloat162(l0, l1);
                    } else {
                        size_t idx = (((size_t)bidx * NH + h) * 64 + d) * LL + l;
                        g_Vh[idx] = h0; g_Vl[idx] = l0;
                        g_Vh[idx + LL] = h1; g_Vl[idx + LL] = l1;
                    }
                }
            }
        }
    }
}

// ============================================================================
// fused attention, TWO PASS, q-tile 64, 2 CTAs/SM.
// pass1: S = (Qh+Ql)Kh, rowsums -> inv. pass2: S 3-MMA, normalized attn +
// P (hi only) -> O += Ph(Vh+Vl).
// smem elems: Qh 0, Ql 4608, Kh 9216, Kl 18432, Vh 27648, Vl 36352, Ph 45056
// total 53760 elems = 107520 B
// ============================================================================
#define SQ 72
#define SV 136
__global__ __launch_bounds__(256, 2) void attn_kernel(const int* __restrict__ mask,
                                                      float* __restrict__ attn){
    extern __shared__ char smraw[];
    __nv_bfloat16* S = (__nv_bfloat16*)smraw;
    __nv_bfloat16 *Qh = S,          *Ql = S + 4608,
                  *Kh = S + 9216,   *Kl = S + 18432,
                  *Vh = S + 27648,  *Vl = S + 36352,
                  *Ph = S + 45056;
    __shared__ float s_msk[128];
    __shared__ float s_rs[64][4];
    __shared__ float s_inv[64];

    const int bh = blockIdx.y, q0 = blockIdx.x * 64, b = bh >> 4;
    const int tid = threadIdx.x, w = tid >> 5, lane = tid & 31;
    const int wq = w >> 2, wn = w & 3;
    const int r = lane >> 2, cq = lane & 3;

    // persistent Q tile [64][64] hi/lo
    #pragma unroll
    for (int i = tid; i < 1024; i += 256) {
        int t = i >> 9, e = i & 511, rr = e >> 3, c8 = e & 7;
        const __nv_bfloat16* src = (t ? g_Ql : g_Qh) + ((size_t)bh * LL + q0) * 64;
        cp16((t ? Ql : Qh) + rr * SQ + c8 * 8, src + (size_t)rr * 64 + c8 * 8);
    }
    CP_COMMIT();

    float rs[2][2] = {{0,0},{0,0}};

    // ---------------- pass 1: rowsums ----------------
    for (int kt = 0; kt < 16; kt++) {
        const int k0g = kt * 128;
        __syncthreads();
        #pragma unroll
        for (int i = tid; i < 1024; i += 256) {
            int rr = i >> 3, c8 = i & 7;
            const __nv_bfloat16* src = g_Kh + ((size_t)bh * LL + k0g) * 64;
            cp16(Kh + rr * SQ + c8 * 8, src + (size_t)rr * 64 + c8 * 8);
        }
        CP_COMMIT();
        if (tid < 128) s_msk[tid] = mask[b * LL + k0g + tid] ? 1.f : 0.f;
        asm volatile("cp.async.wait_group 0;" ::: "memory");
        __syncthreads();

        float Cs[2][4][4];
        #pragma unroll
        for (int i=0;i<2;i++) for (int j=0;j<4;j++) for (int q=0;q<4;q++) Cs[i][j][q]=0.f;
        #pragma unroll
        for (int ks = 0; ks < 4; ks++) {
            uint32_t fbh[4][2];
            #pragma unroll
            for (int nt = 0; nt < 4; nt++)
                ldmB(fbh[nt], Kh, SQ, wn * 32 + nt * 8, ks * 16, lane);
            #pragma unroll
            for (int mt = 0; mt < 2; mt++) {
                uint32_t fah[4], fal[4];
                ldmA(fah, Qh, SQ, wq * 32 + mt * 16, ks * 16, lane);
                ldmA(fal, Ql, SQ, wq * 32 + mt * 16, ks * 16, lane);
                #pragma unroll
                for (int nt = 0; nt < 4; nt++) {
                    mma16816(Cs[mt][nt], fah, fbh[nt]);
                    mma16816(Cs[mt][nt], fal, fbh[nt]);
                }
            }
        }
        #pragma unroll
        for (int mt = 0; mt < 2; mt++)
            #pragma unroll
            for (int nt = 0; nt < 4; nt++) {
                int col = wn * 32 + nt * 8 + 2 * cq;
                float m0 = s_msk[col], m1 = s_msk[col + 1];
                #pragma unroll
                for (int hf = 0; hf < 2; hf++)
                    rs[mt][hf] += __expf(Cs[mt][nt][hf*2+0]) * m0
                                + __expf(Cs[mt][nt][hf*2+1]) * m1;
            }
    }

    #pragma unroll
    for (int mt = 0; mt < 2; mt++)
        #pragma unroll
        for (int hf = 0; hf < 2; hf++) {
            rs[mt][hf] += __shfl_xor_sync(0xffffffffu, rs[mt][hf], 1);
            rs[mt][hf] += __shfl_xor_sync(0xffffffffu, rs[mt][hf], 2);
        }
    __syncthreads();
    if (cq == 0) {
        #pragma unroll
        for (int mt = 0; mt < 2; mt++)
            #pragma unroll
            for (int hf = 0; hf < 2; hf++)
                s_rs[wq * 32 + mt * 16 + r + hf * 8][wn] = rs[mt][hf];
    }
    __syncthreads();
    if (tid < 64)
        s_inv[tid] = 1.f / (s_rs[tid][0] + s_rs[tid][1] + s_rs[tid][2] + s_rs[tid][3]);
    __syncthreads();

    float O[2][2][4];
    #pragma unroll
    for (int i=0;i<2;i++) for (int j=0;j<2;j++) for (int q=0;q<4;q++) O[i][j][q]=0.f;
    float inv_r[2][2];
    #pragma unroll
    for (int mt = 0; mt < 2; mt++)
        #pragma unroll
        for (int hf = 0; hf < 2; hf++)
            inv_r[mt][hf] = s_inv[wq * 32 + mt * 16 + r + hf * 8];

    // ---------------- pass 2 ----------------
    for (int kt = 0; kt < 16; kt++) {
        const int k0g = kt * 128;
        __syncthreads();
        #pragma unroll
        for (int i = tid; i < 2048; i += 256) {
            int t = i >> 10, e = i & 1023, rr = e >> 3, c8 = e & 7;
            const __nv_bfloat16* src = (t ? g_Kl : g_Kh) + ((size_t)bh * LL + k0g) * 64;
            cp16((t ? Kl : Kh) + rr * SQ + c8 * 8, src + (size_t)rr * 64 + c8 * 8);
        }
        #pragma unroll
        for (int i = tid; i < 2048; i += 256) {
            int t = i >> 10, e = i & 1023, rr = e >> 4, c8 = e & 15;
            const __nv_bfloat16* src = (t ? g_Vl : g_Vh) + (size_t)bh * 64 * LL;
            cp16((t ? Vl : Vh) + rr * SV + c8 * 8, src + (size_t)rr * LL + k0g + c8 * 8);
        }
        CP_COMMIT();
        if (tid < 128) s_msk[tid] = mask[b * LL + k0g + tid] ? 1.f : 0.f;
        asm volatile("cp.async.wait_group 0;" ::: "memory");
        __syncthreads();

        float Cs[2][4][4];
        #pragma unroll
        for (int i=0;i<2;i++) for (int j=0;j<4;j++) for (int q=0;q<4;q++) Cs[i][j][q]=0.f;
        #pragma unroll
        for (int ks = 0; ks < 4; ks++) {
            uint32_t fbh[4][2], fbl[4][2];
            #pragma unroll
            for (int nt = 0; nt < 4; nt++) {
                ldmB(fbh[nt], Kh, SQ, wn * 32 + nt * 8, ks * 16, lane);
                ldmB(fbl[nt], Kl, SQ, wn * 32 + nt * 8, ks * 16, lane);
            }
            #pragma unroll
            for (int mt = 0; mt < 2; mt++) {
                uint32_t fah[4], fal[4];
                ldmA(fah, Qh, SQ, wq * 32 + mt * 16, ks * 16, lane);
                ldmA(fal, Ql, SQ, wq * 32 + mt * 16, ks * 16, lane);
                #pragma unroll
                for (int nt = 0; nt < 4; nt++) {
                    mma16816(Cs[mt][nt], fah, fbh[nt]);
                    mma16816(Cs[mt][nt], fah, fbl[nt]);
                    mma16816(Cs[mt][nt], fal, fbh[nt]);
                }
            }
        }

        #pragma unroll
        for (int mt = 0; mt < 2; mt++) {
            #pragma unroll
            for (int nt = 0; nt < 4; nt++) {
                int col = wn * 32 + nt * 8 + 2 * cq;
                float m0 = s_msk[col], m1 = s_msk[col + 1];
                #pragma unroll
                for (int hf = 0; hf < 2; hf++) {
                    int row = wq * 32 + mt * 16 + r + hf * 8;
                    float iv = inv_r[mt][hf];
                    float e0 = __expf(Cs[mt][nt][hf*2+0]) * m0 * iv;
                    float e1 = __expf(Cs[mt][nt][hf*2+1]) * m1 * iv;
                    if (attn)
                        *(float2*)(attn + ((size_t)bh * LL + q0 + row) * LL + k0g + col) =
                            make_float2(e0, e1);
                    *(__nv_bfloat162*)(Ph + (size_t)row * SV + col) =
                        __halves2bfloat162(__float2bfloat16(e0), __float2bfloat16(e1));
                }
            }
        }
        __syncthreads();

        #pragma unroll
        for (int ks = 0; ks < 8; ks++) {
            uint32_t vbh[2][2], vbl[2][2];
            #pragma unroll
            for (int nt = 0; nt < 2; nt++) {
                ldmB(vbh[nt], Vh, SV, wn * 16 + nt * 8, ks * 16, lane);
                ldmB(vbl[nt], Vl, SV, wn * 16 + nt * 8, ks * 16, lane);
            }
            #pragma unroll
            for (int mt = 0; mt < 2; mt++) {
                uint32_t pah[4];
                ldmA(pah, Ph, SV, wq * 32 + mt * 16, ks * 16, lane);
                #pragma unroll
                for (int nt = 0; nt < 2; nt++) {
                    mma16816(O[mt][nt], pah, vbh[nt]);
                    mma16816(O[mt][nt], pah, vbl[nt]);
                }
            }
        }
    }

    // ---- O epilogue ----
    #pragma unroll
    for (int mt = 0; mt < 2; mt++) {
        #pragma unroll
        for (int nt = 0; nt < 2; nt++) {
            int d = wn * 16 + nt * 8 + 2 * cq;
            #pragma unroll
            for (int hf = 0; hf < 2; hf++) {
                int row = wq * 32 + mt * 16 + r + hf * 8;
                __nv_bfloat16 h0,l0,h1,l1;
                split_bf(O[mt][nt][hf*2+0], h0, l0);
                split_bf(O[mt][nt][hf*2+1], h1, l1);
                size_t idx = ((size_t)b * LL + q0 + row) * DM + (bh & 15) * 64 + d;
                *(__nv_bfloat162*)(g_Oh + idx) = __halves2bfloat162(h0, h1);
                *(__nv_bfloat162*)(g_Ol + idx) = __halves2bfloat162(l0, l1);
            }
        }
    }
}

// ============================================================================
extern "C" void kernel_launch(void* const* d_in, const int* in_sizes, int n_in,
                              void* d_out, int out_size)
{
    const float* x    = (const float*)d_in[0];
    const int*   mask = (const int*)  d_in[1];
    const float* bq   = (const float*)d_in[3];
    const float* bk   = (const float*)d_in[5];
    const float* bv   = (const float*)d_in[7];
    const float* bo   = (const float*)d_in[9];
    float* out = (float*)d_out;

    const size_t out_elems  = (size_t)MM * DM;
    const size_t attn_elems = (size_t)BB * NH * LL * LL;
    float* attn = ((size_t)out_size >= out_elems + attn_elems) ? (out + out_elems) : nullptr;

    const int smem_proj = 2 * STG * 2;     // 81920 B
    const int smem_attn = 107520;
    cudaFuncSetAttribute(proj_kernel, cudaFuncAttributeMaxDynamicSharedMemorySize, smem_proj);
    cudaFuncSetAttribute(attn_kernel, cudaFuncAttributeMaxDynamicSharedMemorySize, smem_attn);

    const size_t total_cvt = (size_t)MM * DM + 4 * (size_t)DM * DM;   // 8M elems
    cvt_all_kernel<<<(int)(total_cvt / 4 / 256), 256>>>(
        x, (const float*)d_in[2], (const float*)d_in[4],
        (const float*)d_in[6], (const float*)d_in[8]);

    proj_kernel<<<dim3(8, 32, 3), 256, smem_proj>>>(bq, bk, bv, nullptr, -1);

    attn_kernel<<<dim3(LL / 64, BB * NH), 256, smem_attn>>>(mask, attn);

    proj_kernel<<<dim3(8, 32, 1), 256, smem_proj>>>(bo, nullptr, nullptr, out, 3);
}